// round 10
// baseline (speedup 1.0000x reference)
#include <cuda_runtime.h>
#include <math.h>

#define GD 64
#define SD 32
#define NV (GD*GD*GD)
#define NP (SD*SD*SD)
#define CSTRIDE 10944
#define CH 43

// ---------------- device scratch ----------------
__device__ float g_prob[NV*16];
__device__ float g_hs[8][NV*16];
__device__ float g_h1[NP*16];
__device__ float g_h2[NP*16];
__device__ unsigned char g_occx[NV];
__device__ unsigned char g_pocc[NP];
__device__ unsigned char g_min[NV];
__device__ int g_list_in_c[192*CSTRIDE];
__device__ int g_list_out_c[192*CSTRIDE];
__device__ int g_cnt_in_c[192];
__device__ int g_cnt_out_c[192];

struct K1 {
    const float* w[8]; const float* b[8];
    const float* w20; const float* b20;
    int n_ent;
    int lid[80]; unsigned cand[80]; unsigned char es[80];
};
struct K2 {
    const float* w[8]; const float* b[8];
    int n_ent;
    int lid[32]; unsigned cand[32]; unsigned char es[32];
};

// ---------------- packed f32x2 helpers (kept for k_fel2/k_up where they measured faster) ----------------
__device__ __forceinline__ unsigned long long pk2(float v) {
    unsigned long long r;
    asm("mov.b64 %0, {%1, %1};" : "=l"(r) : "f"(v));
    return r;
}
__device__ __forceinline__ unsigned long long pk2(float lo, float hi) {
    unsigned long long r;
    asm("mov.b64 %0, {%1, %2};" : "=l"(r) : "f"(lo), "f"(hi));
    return r;
}
__device__ __forceinline__ void upk2(unsigned long long v, float& lo, float& hi) {
    asm("mov.b64 {%0, %1}, %2;" : "=f"(lo), "=f"(hi) : "l"(v));
}
__device__ __forceinline__ void f2fma(unsigned long long& d, unsigned long long a, unsigned long long b) {
    asm("fma.rn.f32x2 %0, %1, %2, %0;" : "+l"(d) : "l"(a), "l"(b));
}
__device__ __forceinline__ void gemv16_f2(unsigned long long* A, const float* in,
                                          const float* wrow) {
    const ulonglong2* wp = (const ulonglong2*)wrow;
    #pragma unroll
    for (int cin=0; cin<16; cin++) {
        unsigned long long v2 = pk2(in[cin]);
        ulonglong2 w01 = wp[cin*4+0];
        ulonglong2 w23 = wp[cin*4+1];
        ulonglong2 w45 = wp[cin*4+2];
        ulonglong2 w67 = wp[cin*4+3];
        f2fma(A[0], v2, w01.x); f2fma(A[1], v2, w01.y);
        f2fma(A[2], v2, w23.x); f2fma(A[3], v2, w23.y);
        f2fma(A[4], v2, w45.x); f2fma(A[5], v2, w45.y);
        f2fma(A[6], v2, w67.x); f2fma(A[7], v2, w67.y);
    }
}

// ---------------- init ----------------
__global__ void k_init(const float* __restrict__ x) {
    int p = blockIdx.x*256 + threadIdx.x;
    if (p < 192) { g_cnt_in_c[p] = 0; g_cnt_out_c[p] = 0; }
    if (p >= NP) return;
    int px = p>>10, py = (p>>5)&31, pz = p&31;
    int bx = px<<1, by = py<<1, bz = pz<<1;
    unsigned char o = 0;
    #pragma unroll
    for (int a=0;a<2;a++)
    #pragma unroll
    for (int b=0;b<2;b++)
    #pragma unroll
    for (int c=0;c<2;c++) {
        int v = ((bx+a)<<12)|((by+b)<<6)|(bz+c);
        unsigned char oc = (x[v] > 0.f) ? 1 : 0;
        g_occx[v] = oc;
        o |= oc;
    }
    g_pocc[p] = o;
}

// ---------------- fused: mask/class-lists/labels + FEL conv1 ----------------
__global__ void k_maskfel1(float* __restrict__ out,
                           const float* __restrict__ wf1, const float* __restrict__ bf1) {
    __shared__ int scnt[384];
    __shared__ int sbase[384];
    __shared__ float swf[432];
    __shared__ float sbf[16];
    int tid = threadIdx.x;
    if (blockIdx.x < 1024) {
        for (int i=tid;i<384;i+=256) scnt[i]=0;
        __syncthreads();
        int v = blockIdx.x*256 + tid;
        int x = v>>12, y = (v>>6)&63, z = v&63;
        const int LUT[8] = {0,5,4,3,4,2,1,5};
        int par = ((x&1)<<2)|((y&1)<<1)|(z&1);
        int gid = LUT[par];
        int mid = ((x>>1)+(y>>1)+(z>>1)) % 3;
        int cls = par*3 + mid;
        bool O = g_pocc[((x>>1)<<10)|((y>>1)<<5)|(z>>1)] != 0;
        bool X = g_occx[v] != 0;
        bool g0 = (gid == 0);

        bool bi[8], bo[8];
        bi[0] = O && g0 && (mid==0);
        bi[1] = (O && g0 && mid==1) || (X && g0 && mid==0);
        bi[2] = (X && g0 && mid<2)  || (O && g0 && mid==2);
        bi[3] = (X && g0)      || (O && gid==1);
        bi[4] = (X && gid<=1)  || (O && gid==2);
        bi[5] = (X && gid<=2)  || (O && gid==3);
        bi[6] = (X && gid<=3)  || (O && gid==4);
        bi[7] = (X && gid<=4)  || (O && gid==5);
        bo[0] = O && g0 && mid==0;
        bo[1] = O && g0 && mid==1;
        bo[2] = O && g0 && mid==2;
        #pragma unroll
        for (int s=3;s<8;s++) bo[s] = O && (gid == s-2);

        unsigned char mb = 0;
        int rin[8], rout[8];
        #pragma unroll
        for (int s=0;s<8;s++) {
            if (bi[s]) { mb |= (1u<<s); rin[s]  = atomicAdd(&scnt[s*24+cls],     1); }
            if (bo[s]) {               rout[s] = atomicAdd(&scnt[192+s*24+cls], 1); }
        }
        g_min[v] = mb;
        __syncthreads();
        for (int i=tid;i<384;i+=256) {
            int c = scnt[i];
            sbase[i] = c ? atomicAdd(i<192 ? &g_cnt_in_c[i] : &g_cnt_out_c[i-192], c) : 0;
        }
        __syncthreads();
        #pragma unroll
        for (int s=0;s<8;s++) {
            if (bi[s]) g_list_in_c [(s*24+cls)*CSTRIDE + sbase[s*24+cls]     + rin[s]]  = v;
            if (bo[s]) g_list_out_c[(s*24+cls)*CSTRIDE + sbase[192+s*24+cls] + rout[s]] = v;
        }
        #pragma unroll
        for (int s=0;s<8;s++) out[(s<<18)+v] = 0.f;
        #pragma unroll
        for (int s=0;s<8;s++) {
            bool lab = (s<3) ? (X && g0 && mid==s) : (X && gid==(s-2));
            out[((8+s)<<18)+v] = lab ? 1.f : 0.f;
        }
    } else {
        for (int i=tid;i<432;i+=256) swf[i]=wf1[i];
        if (tid<16) sbf[tid]=bf1[tid];
        __syncthreads();
        int p = (blockIdx.x-1024)*256 + tid;
        if (!g_pocc[p]) return;
        int px=p>>10, py=(p>>5)&31, pz=p&31;
        float acc[16];
        #pragma unroll
        for (int c=0;c<16;c++) acc[c]=sbf[c];
        for (int dx=-1;dx<=1;dx++){ int nx=px+dx; if ((unsigned)nx>=32u) continue;
        for (int dy=-1;dy<=1;dy++){ int ny=py+dy; if ((unsigned)ny>=32u) continue;
        for (int dz=-1;dz<=1;dz++){ int nz=pz+dz; if ((unsigned)nz>=32u) continue;
            if (!g_pocc[(nx<<10)|(ny<<5)|nz]) continue;
            int d = ((dx+1)*3+(dy+1))*3+(dz+1);
            const float* wr = swf + d*16;
            #pragma unroll
            for (int c=0;c<16;c++) acc[c] += wr[c];
        }}}
        float* o = g_h1 + p*16;
        #pragma unroll
        for (int c=0;c<16;c++) o[c] = fmaxf(acc[c],0.f);
    }
}

// ---------------- FEL conv2 (f32x2) ----------------
__global__ void k_fel2(const float* __restrict__ w, const float* __restrict__ b) {
    __shared__ float sw[27*256];
    int tid = threadIdx.x;
    for (int i=tid;i<6912;i+=blockDim.x) sw[i]=w[i];
    __syncthreads();
    int p = blockIdx.x*blockDim.x + tid;
    if (p >= NP) return;
    if (!g_pocc[p]) return;
    unsigned long long A[8];
    #pragma unroll
    for (int j=0;j<8;j++) A[j] = pk2(b[2*j], b[2*j+1]);
    int px=p>>10, py=(p>>5)&31, pz=p&31;
    for (int dx=-1;dx<=1;dx++){ int nx=px+dx; if ((unsigned)nx>=32u) continue;
    for (int dy=-1;dy<=1;dy++){ int ny=py+dy; if ((unsigned)ny>=32u) continue;
    for (int dz=-1;dz<=1;dz++){ int nz=pz+dz; if ((unsigned)nz>=32u) continue;
        int nv = (nx<<10)|(ny<<5)|nz;
        if (!g_pocc[nv]) continue;
        int d = ((dx+1)*3+(dy+1))*3+(dz+1);
        const float4* hp4 = (const float4*)(g_h1 + nv*16);
        float4 h0=hp4[0], h1=hp4[1], h2=hp4[2], h3=hp4[3];
        float in[16] = {h0.x,h0.y,h0.z,h0.w, h1.x,h1.y,h1.z,h1.w,
                        h2.x,h2.y,h2.z,h2.w, h3.x,h3.y,h3.z,h3.w};
        gemv16_f2(A, in, sw + d*256);
    }}}
    float* o = g_h2 + p*16;
    #pragma unroll
    for (int j=0;j<8;j++) upk2(A[j], o[2*j], o[2*j+1]);
}

// ---------------- generative upsample (f32x2) ----------------
__global__ void k_up(const float* __restrict__ wup, const float* __restrict__ bup) {
    __shared__ float sw[8*256];
    __shared__ float sb[16];
    int tid = threadIdx.x;
    for (int i=tid;i<2048;i+=blockDim.x) sw[i]=wup[i];
    if (tid<16) sb[tid]=bup[tid];
    __syncthreads();
    int v = blockIdx.x*blockDim.x + tid;
    if (v >= NV) return;
    int x=v>>12, y=(v>>6)&63, z=v&63;
    int p = ((x>>1)<<10)|((y>>1)<<5)|(z>>1);
    float* po = g_prob + v*16;
    if (!g_pocc[p]) {
        #pragma unroll
        for (int c=0;c<16;c++) po[c]=0.f;
        return;
    }
    int o = ((x&1)<<2)|((y&1)<<1)|(z&1);
    unsigned long long A[8];
    #pragma unroll
    for (int j=0;j<8;j++) A[j] = pk2(sb[2*j], sb[2*j+1]);
    const float4* hp4 = (const float4*)(g_h2 + p*16);
    float4 h0=hp4[0], h1=hp4[1], h2=hp4[2], h3=hp4[3];
    float in[16] = {h0.x,h0.y,h0.z,h0.w, h1.x,h1.y,h1.z,h1.w,
                    h2.x,h2.y,h2.z,h2.w, h3.x,h3.y,h3.z,h3.w};
    gemv16_f2(A, in, sw + o*256);
    #pragma unroll
    for (int j=0;j<8;j++) upk2(A[j], po[2*j], po[2*j+1]);
}

// ---------------- conv1: quad-cooperative voxels (4 lanes/voxel) ----------------
__global__ void __launch_bounds__(256) k_conv1_all(K1 P, float* __restrict__ out) {
    int e = blockIdx.x / CH, ch = blockIdx.x % CH;
    int s = P.es[e];
    int lid = P.lid[e];
    int cnt = g_cnt_in_c[lid];
    if (ch*256 >= cnt) return;
    __shared__ float sw[6944];
    int tid = threadIdx.x;
    int q  = tid >> 2;        // voxel slot within 64-voxel pass
    int l4 = tid & 3;         // cin-quarter lane

    if (s == 0) {
        if (tid < 256) sw[tid] = P.w[0][13*256 + tid];
        if (tid < 16)  sw[6912+tid] = P.w20[13*16 + tid];
        if (tid < 16)  sw[6928+tid] = P.b[0][tid];
        __syncthreads();
        #pragma unroll 1
        for (int it=0; it<4; it++) {
            int base = ch*256 + it*64;
            if (base >= cnt) break;
            int idx = base + q;
            bool valid = idx < cnt;
            int idc = valid ? idx : (cnt-1);
            int v = g_list_in_c[lid*CSTRIDE + idc];
            float4 inq = *(const float4*)(g_prob + v*16 + 4*l4);
            float a[16];
            #pragma unroll
            for (int c=0;c<16;c++) a[c] = (l4==0) ? sw[6928+c] : 0.f;
            #pragma unroll
            for (int j=0;j<4;j++) {
                float vv = (&inq.x)[j];
                const float* wc = sw + (4*l4+j)*16;
                #pragma unroll
                for (int c=0;c<16;c++) a[c] += vv*wc[c];
            }
            #pragma unroll
            for (int c=0;c<16;c++) {
                a[c] += __shfl_xor_sync(0xffffffffu, a[c], 1);
                a[c] += __shfl_xor_sync(0xffffffffu, a[c], 2);
            }
            if (valid && l4==0) {
                float acc = P.b20[0];
                #pragma unroll
                for (int c=0;c<16;c++) acc += fmaxf(a[c],0.f)*sw[6912+c];
                out[v] = 1.f/(1.f + expf(-acc));
            }
        }
        return;
    }

    bool is5 = (s==1 || s==2);
    const float* w = P.w[s];
    if (is5) {
        for (int i=tid;i<6912;i+=256) {
            int t=i>>8, c=i&255;
            int a=t/9, bb=(t/3)%3, cc=t%3;
            sw[i] = w[(((2*a)*5+2*bb)*5+2*cc)*256 + c];
        }
    } else {
        for (int i=tid;i<6912;i+=256) sw[i]=w[i];
    }
    __syncthreads();
    int sc = is5 ? 2 : 1;
    unsigned cand = P.cand[e];
    const float* bb = P.b[s];
    #pragma unroll 1
    for (int it=0; it<4; it++) {
        int base = ch*256 + it*64;
        if (base >= cnt) break;
        int idx = base + q;
        bool valid = idx < cnt;
        int idc = valid ? idx : (cnt-1);
        int v = g_list_in_c[lid*CSTRIDE + idc];
        int x=v>>12, y=(v>>6)&63, z=v&63;
        float A[16];
        #pragma unroll
        for (int c=0;c<16;c++) A[c] = (l4==0) ? bb[c] : 0.f;
        unsigned m = cand;
        while (m) {
            int t = __ffs(m)-1; m &= m-1;
            int nx = x + sc*(t/9-1), ny = y + sc*((t/3)%3-1), nz = z + sc*(t%3-1);
            bool inb = ((unsigned)(nx|ny|nz) < 64u);
            int nvc = ((nx&63)<<12)|((ny&63)<<6)|(nz&63);
            float sel = (inb && ((g_min[nvc]>>s)&1)) ? 1.f : 0.f;
            float4 inq = *(const float4*)(g_prob + nvc*16 + 4*l4);
            inq.x *= sel; inq.y *= sel; inq.z *= sel; inq.w *= sel;
            const float* wr = sw + t*256 + (4*l4)*16;
            #pragma unroll
            for (int j=0;j<4;j++) {
                float vv = (&inq.x)[j];
                const float* wc = wr + j*16;
                #pragma unroll
                for (int c=0;c<16;c++) A[c] += vv*wc[c];
            }
        }
        #pragma unroll
        for (int c=0;c<16;c++) {
            A[c] += __shfl_xor_sync(0xffffffffu, A[c], 1);
            A[c] += __shfl_xor_sync(0xffffffffu, A[c], 2);
        }
        if (valid) {
            float4 r;
            r.x = fmaxf(A[4*l4+0],0.f);
            r.y = fmaxf(A[4*l4+1],0.f);
            r.z = fmaxf(A[4*l4+2],0.f);
            r.w = fmaxf(A[4*l4+3],0.f);
            *(float4*)(&g_hs[s][v*16 + 4*l4]) = r;
        }
    }
}

// ---------------- conv2: quad-cooperative voxels ----------------
__global__ void __launch_bounds__(256) k_conv2_all(K2 P, float* __restrict__ out) {
    int e = blockIdx.x / CH, ch = blockIdx.x % CH;
    int s = P.es[e];
    int lid = P.lid[e];
    int cnt = g_cnt_out_c[lid];
    if (ch*256 >= cnt) return;
    __shared__ float sw[432];
    int tid = threadIdx.x;
    int q  = tid >> 2;
    int l4 = tid & 3;
    bool is5 = (s==1 || s==2);
    const float* w = P.w[s];
    if (is5) {
        for (int i=tid;i<432;i+=256) {
            int t=i>>4, c=i&15;
            int a=t/9, bb=(t/3)%3, cc=t%3;
            sw[i] = w[(((2*a)*5+2*bb)*5+2*cc)*16 + c];
        }
    } else {
        for (int i=tid;i<432;i+=256) sw[i]=w[i];
    }
    __syncthreads();
    int sc = is5 ? 2 : 1;
    unsigned cand = P.cand[e];
    const float* hbase = g_hs[s];
    float bias = P.b[s][0];
    #pragma unroll 1
    for (int it=0; it<4; it++) {
        int base = ch*256 + it*64;
        if (base >= cnt) break;
        int idx = base + q;
        bool valid = idx < cnt;
        int idc = valid ? idx : (cnt-1);
        int v = g_list_out_c[lid*CSTRIDE + idc];
        int x=v>>12, y=(v>>6)&63, z=v&63;
        float acc = 0.f;
        unsigned m = cand;
        while (m) {
            int t = __ffs(m)-1; m &= m-1;
            int nx = x + sc*(t/9-1), ny = y + sc*((t/3)%3-1), nz = z + sc*(t%3-1);
            bool inb = ((unsigned)(nx|ny|nz) < 64u);
            int nvc = ((nx&63)<<12)|((ny&63)<<6)|(nz&63);
            float sel = (inb && ((g_min[nvc]>>s)&1)) ? 1.f : 0.f;
            float4 inq = *(const float4*)(hbase + nvc*16 + 4*l4);
            const float4 w4 = *(const float4*)(sw + t*16 + 4*l4);
            float d = inq.x*w4.x + inq.y*w4.y + inq.z*w4.z + inq.w*w4.w;
            acc += sel*d;
        }
        acc += __shfl_xor_sync(0xffffffffu, acc, 1);
        acc += __shfl_xor_sync(0xffffffffu, acc, 2);
        if (valid && l4==0)
            out[(s<<18)+v] = 1.f/(1.f + expf(-(acc + bias)));
    }
}

// ---------------- host-side class/LUT construction ----------------
static const int GIDH[8] = {0,5,4,3,4,2,1,5};

static bool cand_in(int s, int par, int mid) {
    int gid = GIDH[par];
    if (s==0) return gid==0 && mid==0;
    if (s==1) return gid==0 && mid<2;
    if (s==2) return gid==0;
    return gid <= s-2;
}

static int middelta(int pc, int d) {
    if (d==-2) return -1;
    if (d== 2) return  1;
    if (d== 0) return  0;
    if (pc==0) return d==-1 ? -1 : 0;
    return d==1 ? 1 : 0;
}

static unsigned mask3(int s, int par, int mid) {
    unsigned m=0;
    for (int t=0;t<27;t++) {
        int dx=t/9-1, dy=(t/3)%3-1, dz=t%3-1;
        int pn = par ^ ((((dx&1))<<2)|(((dy&1))<<1)|(dz&1));
        int dm = middelta((par>>2)&1,dx)+middelta((par>>1)&1,dy)+middelta(par&1,dz);
        int mn = ((mid+dm)%3+3)%3;
        if (cand_in(s,pn,mn)) m |= 1u<<t;
    }
    return m;
}

static unsigned mask5(int s, int mid) {
    unsigned m=0;
    for (int t=0;t<27;t++) {
        int dx=2*(t/9-1), dy=2*((t/3)%3-1), dz=2*(t%3-1);
        int dm=(dx+dy+dz)/2;
        int mn=((mid+dm)%3+3)%3;
        if (cand_in(s,0,mn)) m |= 1u<<t;
    }
    return m;
}

static bool out_class(int s, int par, int mid) {
    int gid = GIDH[par];
    if (s<3) return gid==0 && mid==s;
    return gid == s-2;
}

// ---------------- launch ----------------
extern "C" void kernel_launch(void* const* d_in, const int* in_sizes, int n_in,
                              void* d_out, int out_size) {
    const float* x      = (const float*)d_in[0];
    const float* w_fel1 = (const float*)d_in[3];
    const float* b_fel1 = (const float*)d_in[4];
    const float* w_fel2 = (const float*)d_in[5];
    const float* b_fel2 = (const float*)d_in[6];
    const float* w_up   = (const float*)d_in[7];
    const float* b_up   = (const float*)d_in[8];
    const float* wc1    = (const float*)d_in[9];
    const float* bc1    = (const float*)d_in[10];
    const float* wc2    = (const float*)d_in[11];
    const float* bc2    = (const float*)d_in[12];
    const float* wl1    = (const float*)d_in[13];
    const float* bl1    = (const float*)d_in[14];
    const float* wl2    = (const float*)d_in[15];
    const float* bl2    = (const float*)d_in[16];
    float* out = (float*)d_out;

    K1 p1; K2 p2;
    for (int s=0;s<8;s++) {
        if (s==1 || s==2) {
            p1.w[s] = wl1 + (s-1)*125*256; p1.b[s] = bl1 + (s-1)*16;
            p2.w[s] = wl2 + (s-1)*125*16;  p2.b[s] = bl2 + (s-1);
        } else {
            int k = (s==0) ? 0 : (s-2);
            p1.w[s] = wc1 + k*27*256; p1.b[s] = bc1 + k*16;
            p2.w[s] = wc2 + k*27*16;  p2.b[s] = bc2 + k;
        }
    }
    p1.w20 = wc2; p1.b20 = bc2;

    int n1 = 0;
    for (int s=0;s<8;s++)
        for (int par=0;par<8;par++)
            for (int mid=0;mid<3;mid++)
                if (cand_in(s,par,mid)) {
                    p1.es[n1]  = (unsigned char)s;
                    p1.lid[n1] = s*24 + par*3 + mid;
                    p1.cand[n1] = (s==0) ? (1u<<13)
                                : (s<=2) ? mask5(s,mid)
                                         : mask3(s,par,mid);
                    n1++;
                }
    p1.n_ent = n1;

    int n2 = 0;
    for (int s=1;s<8;s++)
        for (int par=0;par<8;par++)
            for (int mid=0;mid<3;mid++)
                if (out_class(s,par,mid)) {
                    p2.es[n2]  = (unsigned char)s;
                    p2.lid[n2] = s*24 + par*3 + mid;
                    p2.cand[n2] = (s<=2) ? mask5(s,mid) : mask3(s,par,mid);
                    n2++;
                }
    p2.n_ent = n2;

    k_init<<<128,256>>>(x);
    k_maskfel1<<<1152,256>>>(out, w_fel1, b_fel1);
    k_fel2<<<128,256>>>(w_fel2, b_fel2);
    k_up<<<1024,256>>>(w_up, b_up);
    k_conv1_all<<<n1*CH,256>>>(p1, out);
    k_conv2_all<<<n2*CH,256>>>(p2, out);
}

// round 11
// speedup vs baseline: 2.7394x; 2.7394x over previous
#include <cuda_runtime.h>
#include <math.h>

#define GD 64
#define SD 32
#define NV (GD*GD*GD)
#define NP (SD*SD*SD)
#define CSTRIDE 10944
#define CH 43
#define TP 288            // padded floats per tap (4 slices of 64, stride 72)

// ---------------- device scratch ----------------
__device__ float g_prob[NV*16];
__device__ float g_hs[8][NV*16];
__device__ float g_h1[NP*16];
__device__ float g_h2[NP*16];
__device__ unsigned char g_occx[NV];
__device__ unsigned char g_pocc[NP];
__device__ unsigned char g_min[NV];
__device__ int g_list_in_c[192*CSTRIDE];
__device__ int g_list_out_c[192*CSTRIDE];
__device__ int g_cnt_in_c[192];
__device__ int g_cnt_out_c[192];

struct K1 {
    const float* w[8]; const float* b[8];
    const float* w20; const float* b20;
    int n_ent;
    int lid[80]; unsigned cand[80]; unsigned char es[80];
};
struct K2 {
    const float* w[8]; const float* b[8];
    int n_ent;
    int lid[32]; unsigned cand[32]; unsigned char es[32];
};

// ---------------- packed f32x2 helpers ----------------
__device__ __forceinline__ unsigned long long pk2(float v) {
    unsigned long long r;
    asm("mov.b64 %0, {%1, %1};" : "=l"(r) : "f"(v));
    return r;
}
__device__ __forceinline__ unsigned long long pk2(float lo, float hi) {
    unsigned long long r;
    asm("mov.b64 %0, {%1, %2};" : "=l"(r) : "f"(lo), "f"(hi));
    return r;
}
__device__ __forceinline__ void upk2(unsigned long long v, float& lo, float& hi) {
    asm("mov.b64 {%0, %1}, %2;" : "=f"(lo), "=f"(hi) : "l"(v));
}
__device__ __forceinline__ void f2fma(unsigned long long& d, unsigned long long a, unsigned long long b) {
    asm("fma.rn.f32x2 %0, %1, %2, %0;" : "+l"(d) : "l"(a), "l"(b));
}
__device__ __forceinline__ void gemv16_f2(unsigned long long* A, const float* in,
                                          const float* wrow) {
    const ulonglong2* wp = (const ulonglong2*)wrow;
    #pragma unroll
    for (int cin=0; cin<16; cin++) {
        unsigned long long v2 = pk2(in[cin]);
        ulonglong2 w01 = wp[cin*4+0];
        ulonglong2 w23 = wp[cin*4+1];
        ulonglong2 w45 = wp[cin*4+2];
        ulonglong2 w67 = wp[cin*4+3];
        f2fma(A[0], v2, w01.x); f2fma(A[1], v2, w01.y);
        f2fma(A[2], v2, w23.x); f2fma(A[3], v2, w23.y);
        f2fma(A[4], v2, w45.x); f2fma(A[5], v2, w45.y);
        f2fma(A[6], v2, w67.x); f2fma(A[7], v2, w67.y);
    }
}

// ---------------- init ----------------
__global__ void k_init(const float* __restrict__ x) {
    int p = blockIdx.x*256 + threadIdx.x;
    if (p < 192) { g_cnt_in_c[p] = 0; g_cnt_out_c[p] = 0; }
    if (p >= NP) return;
    int px = p>>10, py = (p>>5)&31, pz = p&31;
    int bx = px<<1, by = py<<1, bz = pz<<1;
    unsigned char o = 0;
    #pragma unroll
    for (int a=0;a<2;a++)
    #pragma unroll
    for (int b=0;b<2;b++)
    #pragma unroll
    for (int c=0;c<2;c++) {
        int v = ((bx+a)<<12)|((by+b)<<6)|(bz+c);
        unsigned char oc = (x[v] > 0.f) ? 1 : 0;
        g_occx[v] = oc;
        o |= oc;
    }
    g_pocc[p] = o;
}

// ---------------- fused: mask/class-lists/labels + FEL conv1 ----------------
__global__ void k_maskfel1(float* __restrict__ out,
                           const float* __restrict__ wf1, const float* __restrict__ bf1) {
    __shared__ int scnt[384];
    __shared__ int sbase[384];
    __shared__ float swf[432];
    __shared__ float sbf[16];
    int tid = threadIdx.x;
    if (blockIdx.x < 1024) {
        for (int i=tid;i<384;i+=256) scnt[i]=0;
        __syncthreads();
        int v = blockIdx.x*256 + tid;
        int x = v>>12, y = (v>>6)&63, z = v&63;
        const int LUT[8] = {0,5,4,3,4,2,1,5};
        int par = ((x&1)<<2)|((y&1)<<1)|(z&1);
        int gid = LUT[par];
        int mid = ((x>>1)+(y>>1)+(z>>1)) % 3;
        int cls = par*3 + mid;
        bool O = g_pocc[((x>>1)<<10)|((y>>1)<<5)|(z>>1)] != 0;
        bool X = g_occx[v] != 0;
        bool g0 = (gid == 0);

        bool bi[8], bo[8];
        bi[0] = O && g0 && (mid==0);
        bi[1] = (O && g0 && mid==1) || (X && g0 && mid==0);
        bi[2] = (X && g0 && mid<2)  || (O && g0 && mid==2);
        bi[3] = (X && g0)      || (O && gid==1);
        bi[4] = (X && gid<=1)  || (O && gid==2);
        bi[5] = (X && gid<=2)  || (O && gid==3);
        bi[6] = (X && gid<=3)  || (O && gid==4);
        bi[7] = (X && gid<=4)  || (O && gid==5);
        bo[0] = O && g0 && mid==0;
        bo[1] = O && g0 && mid==1;
        bo[2] = O && g0 && mid==2;
        #pragma unroll
        for (int s=3;s<8;s++) bo[s] = O && (gid == s-2);

        unsigned char mb = 0;
        int rin[8], rout[8];
        #pragma unroll
        for (int s=0;s<8;s++) {
            if (bi[s]) { mb |= (1u<<s); rin[s]  = atomicAdd(&scnt[s*24+cls],     1); }
            if (bo[s]) {               rout[s] = atomicAdd(&scnt[192+s*24+cls], 1); }
        }
        g_min[v] = mb;
        __syncthreads();
        for (int i=tid;i<384;i+=256) {
            int c = scnt[i];
            sbase[i] = c ? atomicAdd(i<192 ? &g_cnt_in_c[i] : &g_cnt_out_c[i-192], c) : 0;
        }
        __syncthreads();
        #pragma unroll
        for (int s=0;s<8;s++) {
            if (bi[s]) g_list_in_c [(s*24+cls)*CSTRIDE + sbase[s*24+cls]     + rin[s]]  = v;
            if (bo[s]) g_list_out_c[(s*24+cls)*CSTRIDE + sbase[192+s*24+cls] + rout[s]] = v;
        }
        #pragma unroll
        for (int s=0;s<8;s++) out[(s<<18)+v] = 0.f;
        #pragma unroll
        for (int s=0;s<8;s++) {
            bool lab = (s<3) ? (X && g0 && mid==s) : (X && gid==(s-2));
            out[((8+s)<<18)+v] = lab ? 1.f : 0.f;
        }
    } else {
        for (int i=tid;i<432;i+=256) swf[i]=wf1[i];
        if (tid<16) sbf[tid]=bf1[tid];
        __syncthreads();
        int p = (blockIdx.x-1024)*256 + tid;
        if (!g_pocc[p]) return;
        int px=p>>10, py=(p>>5)&31, pz=p&31;
        float acc[16];
        #pragma unroll
        for (int c=0;c<16;c++) acc[c]=sbf[c];
        for (int dx=-1;dx<=1;dx++){ int nx=px+dx; if ((unsigned)nx>=32u) continue;
        for (int dy=-1;dy<=1;dy++){ int ny=py+dy; if ((unsigned)ny>=32u) continue;
        for (int dz=-1;dz<=1;dz++){ int nz=pz+dz; if ((unsigned)nz>=32u) continue;
            if (!g_pocc[(nx<<10)|(ny<<5)|nz]) continue;
            int d = ((dx+1)*3+(dy+1))*3+(dz+1);
            const float* wr = swf + d*16;
            #pragma unroll
            for (int c=0;c<16;c++) acc[c] += wr[c];
        }}}
        float* o = g_h1 + p*16;
        #pragma unroll
        for (int c=0;c<16;c++) o[c] = fmaxf(acc[c],0.f);
    }
}

// ---------------- FEL conv2 (f32x2) ----------------
__global__ void k_fel2(const float* __restrict__ w, const float* __restrict__ b) {
    __shared__ float sw[27*256];
    int tid = threadIdx.x;
    for (int i=tid;i<6912;i+=blockDim.x) sw[i]=w[i];
    __syncthreads();
    int p = blockIdx.x*blockDim.x + tid;
    if (p >= NP) return;
    if (!g_pocc[p]) return;
    unsigned long long A[8];
    #pragma unroll
    for (int j=0;j<8;j++) A[j] = pk2(b[2*j], b[2*j+1]);
    int px=p>>10, py=(p>>5)&31, pz=p&31;
    for (int dx=-1;dx<=1;dx++){ int nx=px+dx; if ((unsigned)nx>=32u) continue;
    for (int dy=-1;dy<=1;dy++){ int ny=py+dy; if ((unsigned)ny>=32u) continue;
    for (int dz=-1;dz<=1;dz++){ int nz=pz+dz; if ((unsigned)nz>=32u) continue;
        int nv = (nx<<10)|(ny<<5)|nz;
        if (!g_pocc[nv]) continue;
        int d = ((dx+1)*3+(dy+1))*3+(dz+1);
        const float4* hp4 = (const float4*)(g_h1 + nv*16);
        float4 h0=hp4[0], h1=hp4[1], h2=hp4[2], h3=hp4[3];
        float in[16] = {h0.x,h0.y,h0.z,h0.w, h1.x,h1.y,h1.z,h1.w,
                        h2.x,h2.y,h2.z,h2.w, h3.x,h3.y,h3.z,h3.w};
        gemv16_f2(A, in, sw + d*256);
    }}}
    float* o = g_h2 + p*16;
    #pragma unroll
    for (int j=0;j<8;j++) upk2(A[j], o[2*j], o[2*j+1]);
}

// ---------------- generative upsample (f32x2) ----------------
__global__ void k_up(const float* __restrict__ wup, const float* __restrict__ bup) {
    __shared__ float sw[8*256];
    __shared__ float sb[16];
    int tid = threadIdx.x;
    for (int i=tid;i<2048;i+=blockDim.x) sw[i]=wup[i];
    if (tid<16) sb[tid]=bup[tid];
    __syncthreads();
    int v = blockIdx.x*blockDim.x + tid;
    if (v >= NV) return;
    int x=v>>12, y=(v>>6)&63, z=v&63;
    int p = ((x>>1)<<10)|((y>>1)<<5)|(z>>1);
    float* po = g_prob + v*16;
    if (!g_pocc[p]) {
        #pragma unroll
        for (int c=0;c<16;c++) po[c]=0.f;
        return;
    }
    int o = ((x&1)<<2)|((y&1)<<1)|(z&1);
    unsigned long long A[8];
    #pragma unroll
    for (int j=0;j<8;j++) A[j] = pk2(sb[2*j], sb[2*j+1]);
    const float4* hp4 = (const float4*)(g_h2 + p*16);
    float4 h0=hp4[0], h1=hp4[1], h2=hp4[2], h3=hp4[3];
    float in[16] = {h0.x,h0.y,h0.z,h0.w, h1.x,h1.y,h1.z,h1.w,
                    h2.x,h2.y,h2.z,h2.w, h3.x,h3.y,h3.z,h3.w};
    gemv16_f2(A, in, sw + o*256);
    #pragma unroll
    for (int j=0;j<8;j++) upk2(A[j], po[2*j], po[2*j+1]);
}

// ---------------- conv1: quad voxels, bank-conflict-free padded weights ----------------
// layout: sw[t*TP + l4*72 + j*16 + c]  (j = cin within lane's quarter, c = cout)
// banks across quad lanes: l4*72 mod 32 = l4*8 -> 0/8/16/24, conflict-free; same-l4 lanes broadcast.
__global__ void __launch_bounds__(256) k_conv1_all(K1 P, float* __restrict__ out) {
    int e = blockIdx.x / CH, ch = blockIdx.x % CH;
    int s = P.es[e];
    int lid = P.lid[e];
    int cnt = g_cnt_in_c[lid];
    if (ch*256 >= cnt) return;
    __shared__ float sw[27*TP + 304];       // 7776 + stage0 area
    int tid = threadIdx.x;
    int q  = tid >> 2;
    int l4 = tid & 3;

    if (s == 0) {
        // per-thread fused pointwise coder (R7-proven path)
        if (tid < 256) sw[7776+tid] = P.w[0][13*256 + tid];
        if (tid < 16)  sw[8032+tid] = P.w20[13*16 + tid];
        if (tid < 16)  sw[8048+tid] = P.b[0][tid];
        __syncthreads();
        int idx = ch*256 + tid;
        if (idx >= cnt) return;
        int v = g_list_in_c[lid*CSTRIDE + idx];
        const float4* pin = (const float4*)(g_prob + v*16);
        float4 i0=pin[0], i1=pin[1], i2=pin[2], i3=pin[3];
        float in[16] = {i0.x,i0.y,i0.z,i0.w, i1.x,i1.y,i1.z,i1.w,
                        i2.x,i2.y,i2.z,i2.w, i3.x,i3.y,i3.z,i3.w};
        float a[16];
        #pragma unroll
        for (int c=0;c<16;c++) a[c]=sw[8048+c];
        #pragma unroll
        for (int cin=0;cin<16;cin++){
            float vv = in[cin];
            #pragma unroll
            for (int c=0;c<16;c++) a[c] += vv*sw[7776+cin*16+c];
        }
        float acc = P.b20[0];
        #pragma unroll
        for (int c=0;c<16;c++) acc += fmaxf(a[c],0.f)*sw[8032+c];
        out[v] = 1.f/(1.f + expf(-acc));
        return;
    }

    bool is5 = (s==1 || s==2);
    const float* w = P.w[s];
    // stage weights into padded layout
    for (int i=tid;i<6912;i+=256) {
        int t = i>>8, r = i&255;
        int cin = r>>4, c = r&15;
        int src;
        if (is5) {
            int a=t/9, bb=(t/3)%3, cc=t%3;
            src = (((2*a)*5+2*bb)*5+2*cc)*256 + r;
        } else {
            src = i;
        }
        sw[t*TP + (cin>>2)*72 + (cin&3)*16 + c] = w[src];
    }
    __syncthreads();
    int sc = is5 ? 2 : 1;
    unsigned cand = P.cand[e];
    const float* bb = P.b[s];
    #pragma unroll 1
    for (int it=0; it<4; it++) {
        int base = ch*256 + it*64;
        if (base >= cnt) break;
        int idx = base + q;
        bool valid = idx < cnt;
        int idc = valid ? idx : (cnt-1);
        int v = g_list_in_c[lid*CSTRIDE + idc];
        int x=v>>12, y=(v>>6)&63, z=v&63;
        float A[16];
        #pragma unroll
        for (int c=0;c<16;c++) A[c] = (l4==0) ? bb[c] : 0.f;
        unsigned m = cand;
        while (m) {
            int t = __ffs(m)-1; m &= m-1;
            int nx = x + sc*(t/9-1), ny = y + sc*((t/3)%3-1), nz = z + sc*(t%3-1);
            bool inb = ((unsigned)(nx|ny|nz) < 64u);
            int nvc = ((nx&63)<<12)|((ny&63)<<6)|(nz&63);
            float sel = (inb && ((g_min[nvc]>>s)&1)) ? 1.f : 0.f;
            float4 inq = *(const float4*)(g_prob + nvc*16 + 4*l4);
            inq.x *= sel; inq.y *= sel; inq.z *= sel; inq.w *= sel;
            const float* wr = sw + t*TP + l4*72;
            #pragma unroll
            for (int j=0;j<4;j++) {
                float vv = (&inq.x)[j];
                const float* wc = wr + j*16;
                #pragma unroll
                for (int c=0;c<16;c++) A[c] += vv*wc[c];
            }
        }
        #pragma unroll
        for (int c=0;c<16;c++) {
            A[c] += __shfl_xor_sync(0xffffffffu, A[c], 1);
            A[c] += __shfl_xor_sync(0xffffffffu, A[c], 2);
        }
        if (valid) {
            float4 r;
            r.x = fmaxf(A[4*l4+0],0.f);
            r.y = fmaxf(A[4*l4+1],0.f);
            r.z = fmaxf(A[4*l4+2],0.f);
            r.w = fmaxf(A[4*l4+3],0.f);
            *(float4*)(&g_hs[s][v*16 + 4*l4]) = r;
        }
    }
}

// ---------------- conv2: quad voxels (weight layout already conflict-free) ----------------
__global__ void __launch_bounds__(256) k_conv2_all(K2 P, float* __restrict__ out) {
    int e = blockIdx.x / CH, ch = blockIdx.x % CH;
    int s = P.es[e];
    int lid = P.lid[e];
    int cnt = g_cnt_out_c[lid];
    if (ch*256 >= cnt) return;
    __shared__ float sw[432];
    int tid = threadIdx.x;
    int q  = tid >> 2;
    int l4 = tid & 3;
    bool is5 = (s==1 || s==2);
    const float* w = P.w[s];
    if (is5) {
        for (int i=tid;i<432;i+=256) {
            int t=i>>4, c=i&15;
            int a=t/9, bb=(t/3)%3, cc=t%3;
            sw[i] = w[(((2*a)*5+2*bb)*5+2*cc)*16 + c];
        }
    } else {
        for (int i=tid;i<432;i+=256) sw[i]=w[i];
    }
    __syncthreads();
    int sc = is5 ? 2 : 1;
    unsigned cand = P.cand[e];
    const float* hbase = g_hs[s];
    float bias = P.b[s][0];
    #pragma unroll 1
    for (int it=0; it<4; it++) {
        int base = ch*256 + it*64;
        if (base >= cnt) break;
        int idx = base + q;
        bool valid = idx < cnt;
        int idc = valid ? idx : (cnt-1);
        int v = g_list_out_c[lid*CSTRIDE + idc];
        int x=v>>12, y=(v>>6)&63, z=v&63;
        float acc = 0.f;
        unsigned m = cand;
        while (m) {
            int t = __ffs(m)-1; m &= m-1;
            int nx = x + sc*(t/9-1), ny = y + sc*((t/3)%3-1), nz = z + sc*(t%3-1);
            bool inb = ((unsigned)(nx|ny|nz) < 64u);
            int nvc = ((nx&63)<<12)|((ny&63)<<6)|(nz&63);
            float sel = (inb && ((g_min[nvc]>>s)&1)) ? 1.f : 0.f;
            float4 inq = *(const float4*)(hbase + nvc*16 + 4*l4);
            const float4 w4 = *(const float4*)(sw + t*16 + 4*l4);
            float d = inq.x*w4.x + inq.y*w4.y + inq.z*w4.z + inq.w*w4.w;
            acc += sel*d;
        }
        acc += __shfl_xor_sync(0xffffffffu, acc, 1);
        acc += __shfl_xor_sync(0xffffffffu, acc, 2);
        if (valid && l4==0)
            out[(s<<18)+v] = 1.f/(1.f + expf(-(acc + bias)));
    }
}

// ---------------- host-side class/LUT construction ----------------
static const int GIDH[8] = {0,5,4,3,4,2,1,5};

static bool cand_in(int s, int par, int mid) {
    int gid = GIDH[par];
    if (s==0) return gid==0 && mid==0;
    if (s==1) return gid==0 && mid<2;
    if (s==2) return gid==0;
    return gid <= s-2;
}

static int middelta(int pc, int d) {
    if (d==-2) return -1;
    if (d== 2) return  1;
    if (d== 0) return  0;
    if (pc==0) return d==-1 ? -1 : 0;
    return d==1 ? 1 : 0;
}

static unsigned mask3(int s, int par, int mid) {
    unsigned m=0;
    for (int t=0;t<27;t++) {
        int dx=t/9-1, dy=(t/3)%3-1, dz=t%3-1;
        int pn = par ^ ((((dx&1))<<2)|(((dy&1))<<1)|(dz&1));
        int dm = middelta((par>>2)&1,dx)+middelta((par>>1)&1,dy)+middelta(par&1,dz);
        int mn = ((mid+dm)%3+3)%3;
        if (cand_in(s,pn,mn)) m |= 1u<<t;
    }
    return m;
}

static unsigned mask5(int s, int mid) {
    unsigned m=0;
    for (int t=0;t<27;t++) {
        int dx=2*(t/9-1), dy=2*((t/3)%3-1), dz=2*(t%3-1);
        int dm=(dx+dy+dz)/2;
        int mn=((mid+dm)%3+3)%3;
        if (cand_in(s,0,mn)) m |= 1u<<t;
    }
    return m;
}

static bool out_class(int s, int par, int mid) {
    int gid = GIDH[par];
    if (s<3) return gid==0 && mid==s;
    return gid == s-2;
}

// ---------------- launch ----------------
extern "C" void kernel_launch(void* const* d_in, const int* in_sizes, int n_in,
                              void* d_out, int out_size) {
    const float* x      = (const float*)d_in[0];
    const float* w_fel1 = (const float*)d_in[3];
    const float* b_fel1 = (const float*)d_in[4];
    const float* w_fel2 = (const float*)d_in[5];
    const float* b_fel2 = (const float*)d_in[6];
    const float* w_up   = (const float*)d_in[7];
    const float* b_up   = (const float*)d_in[8];
    const float* wc1    = (const float*)d_in[9];
    const float* bc1    = (const float*)d_in[10];
    const float* wc2    = (const float*)d_in[11];
    const float* bc2    = (const float*)d_in[12];
    const float* wl1    = (const float*)d_in[13];
    const float* bl1    = (const float*)d_in[14];
    const float* wl2    = (const float*)d_in[15];
    const float* bl2    = (const float*)d_in[16];
    float* out = (float*)d_out;

    K1 p1; K2 p2;
    for (int s=0;s<8;s++) {
        if (s==1 || s==2) {
            p1.w[s] = wl1 + (s-1)*125*256; p1.b[s] = bl1 + (s-1)*16;
            p2.w[s] = wl2 + (s-1)*125*16;  p2.b[s] = bl2 + (s-1);
        } else {
            int k = (s==0) ? 0 : (s-2);
            p1.w[s] = wc1 + k*27*256; p1.b[s] = bc1 + k*16;
            p2.w[s] = wc2 + k*27*16;  p2.b[s] = bc2 + k;
        }
    }
    p1.w20 = wc2; p1.b20 = bc2;

    int n1 = 0;
    for (int s=0;s<8;s++)
        for (int par=0;par<8;par++)
            for (int mid=0;mid<3;mid++)
                if (cand_in(s,par,mid)) {
                    p1.es[n1]  = (unsigned char)s;
                    p1.lid[n1] = s*24 + par*3 + mid;
                    p1.cand[n1] = (s==0) ? (1u<<13)
                                : (s<=2) ? mask5(s,mid)
                                         : mask3(s,par,mid);
                    n1++;
                }
    p1.n_ent = n1;

    int n2 = 0;
    for (int s=1;s<8;s++)
        for (int par=0;par<8;par++)
            for (int mid=0;mid<3;mid++)
                if (out_class(s,par,mid)) {
                    p2.es[n2]  = (unsigned char)s;
                    p2.lid[n2] = s*24 + par*3 + mid;
                    p2.cand[n2] = (s<=2) ? mask5(s,mid) : mask3(s,par,mid);
                    n2++;
                }
    p2.n_ent = n2;

    k_init<<<128,256>>>(x);
    k_maskfel1<<<1152,256>>>(out, w_fel1, b_fel1);
    k_fel2<<<128,256>>>(w_fel2, b_fel2);
    k_up<<<1024,256>>>(w_up, b_up);
    k_conv1_all<<<n1*CH,256>>>(p1, out);
    k_conv2_all<<<n2*CH,256>>>(p2, out);
}

// round 12
// speedup vs baseline: 3.1958x; 1.1666x over previous
#include <cuda_runtime.h>
#include <math.h>

#define GD 64
#define SD 32
#define NV (GD*GD*GD)
#define NP (SD*SD*SD)
#define CSTRIDE 10944
#define CH 43             // conv2 chunks of 256
#define CH2 22            // conv1 chunks of 512 (2 voxels/thread)

// ---------------- device scratch ----------------
__device__ float g_prob[NV*16];
__device__ float g_hs[8][NV*16];
__device__ float g_h1[NP*16];
__device__ unsigned char g_occx[NV];
__device__ unsigned char g_pocc[NP];
__device__ unsigned char g_min[NV];
__device__ int g_list_in_c[192*CSTRIDE];
__device__ int g_list_out_c[192*CSTRIDE];
__device__ int g_cnt_in_c[192];
__device__ int g_cnt_out_c[192];

struct K1 {
    const float* w[8]; const float* b[8];
    const float* w20; const float* b20;
    int n_ent;
    int lid[80]; unsigned cand[80]; unsigned char es[80];
};
struct K2 {
    const float* w[8]; const float* b[8];
    int n_ent;
    int lid[32]; unsigned cand[32]; unsigned char es[32];
};

// ---------------- packed f32x2 helpers ----------------
__device__ __forceinline__ unsigned long long pk2(float v) {
    unsigned long long r;
    asm("mov.b64 %0, {%1, %1};" : "=l"(r) : "f"(v));
    return r;
}
__device__ __forceinline__ unsigned long long pk2(float lo, float hi) {
    unsigned long long r;
    asm("mov.b64 %0, {%1, %2};" : "=l"(r) : "f"(lo), "f"(hi));
    return r;
}
__device__ __forceinline__ void upk2(unsigned long long v, float& lo, float& hi) {
    asm("mov.b64 {%0, %1}, %2;" : "=f"(lo), "=f"(hi) : "l"(v));
}
__device__ __forceinline__ void f2fma(unsigned long long& d, unsigned long long a, unsigned long long b) {
    asm("fma.rn.f32x2 %0, %1, %2, %0;" : "+l"(d) : "l"(a), "l"(b));
}
__device__ __forceinline__ void gemv16_f2(unsigned long long* A, const float* in,
                                          const float* wrow) {
    const ulonglong2* wp = (const ulonglong2*)wrow;
    #pragma unroll
    for (int cin=0; cin<16; cin++) {
        unsigned long long v2 = pk2(in[cin]);
        ulonglong2 w01 = wp[cin*4+0];
        ulonglong2 w23 = wp[cin*4+1];
        ulonglong2 w45 = wp[cin*4+2];
        ulonglong2 w67 = wp[cin*4+3];
        f2fma(A[0], v2, w01.x); f2fma(A[1], v2, w01.y);
        f2fma(A[2], v2, w23.x); f2fma(A[3], v2, w23.y);
        f2fma(A[4], v2, w45.x); f2fma(A[5], v2, w45.y);
        f2fma(A[6], v2, w67.x); f2fma(A[7], v2, w67.y);
    }
}

// ---------------- init ----------------
__global__ void k_init(const float* __restrict__ x) {
    int p = blockIdx.x*256 + threadIdx.x;
    if (p < 192) { g_cnt_in_c[p] = 0; g_cnt_out_c[p] = 0; }
    if (p >= NP) return;
    int px = p>>10, py = (p>>5)&31, pz = p&31;
    int bx = px<<1, by = py<<1, bz = pz<<1;
    unsigned char o = 0;
    #pragma unroll
    for (int a=0;a<2;a++)
    #pragma unroll
    for (int b=0;b<2;b++)
    #pragma unroll
    for (int c=0;c<2;c++) {
        int v = ((bx+a)<<12)|((by+b)<<6)|(bz+c);
        unsigned char oc = (x[v] > 0.f) ? 1 : 0;
        g_occx[v] = oc;
        o |= oc;
    }
    g_pocc[p] = o;
}

// ---------------- fused: mask/class-lists/labels + FEL conv1 ----------------
__global__ void k_maskfel1(float* __restrict__ out,
                           const float* __restrict__ wf1, const float* __restrict__ bf1) {
    __shared__ int scnt[384];
    __shared__ int sbase[384];
    __shared__ float swf[432];
    __shared__ float sbf[16];
    int tid = threadIdx.x;
    if (blockIdx.x < 1024) {
        for (int i=tid;i<384;i+=256) scnt[i]=0;
        __syncthreads();
        int v = blockIdx.x*256 + tid;
        int x = v>>12, y = (v>>6)&63, z = v&63;
        const int LUT[8] = {0,5,4,3,4,2,1,5};
        int par = ((x&1)<<2)|((y&1)<<1)|(z&1);
        int gid = LUT[par];
        int mid = ((x>>1)+(y>>1)+(z>>1)) % 3;
        int cls = par*3 + mid;
        bool O = g_pocc[((x>>1)<<10)|((y>>1)<<5)|(z>>1)] != 0;
        bool X = g_occx[v] != 0;
        bool g0 = (gid == 0);

        bool bi[8], bo[8];
        bi[0] = O && g0 && (mid==0);
        bi[1] = (O && g0 && mid==1) || (X && g0 && mid==0);
        bi[2] = (X && g0 && mid<2)  || (O && g0 && mid==2);
        bi[3] = (X && g0)      || (O && gid==1);
        bi[4] = (X && gid<=1)  || (O && gid==2);
        bi[5] = (X && gid<=2)  || (O && gid==3);
        bi[6] = (X && gid<=3)  || (O && gid==4);
        bi[7] = (X && gid<=4)  || (O && gid==5);
        bo[0] = O && g0 && mid==0;
        bo[1] = O && g0 && mid==1;
        bo[2] = O && g0 && mid==2;
        #pragma unroll
        for (int s=3;s<8;s++) bo[s] = O && (gid == s-2);

        unsigned char mb = 0;
        int rin[8], rout[8];
        #pragma unroll
        for (int s=0;s<8;s++) {
            if (bi[s]) { mb |= (1u<<s); rin[s]  = atomicAdd(&scnt[s*24+cls],     1); }
            if (bo[s]) {               rout[s] = atomicAdd(&scnt[192+s*24+cls], 1); }
        }
        g_min[v] = mb;
        __syncthreads();
        for (int i=tid;i<384;i+=256) {
            int c = scnt[i];
            sbase[i] = c ? atomicAdd(i<192 ? &g_cnt_in_c[i] : &g_cnt_out_c[i-192], c) : 0;
        }
        __syncthreads();
        #pragma unroll
        for (int s=0;s<8;s++) {
            if (bi[s]) g_list_in_c [(s*24+cls)*CSTRIDE + sbase[s*24+cls]     + rin[s]]  = v;
            if (bo[s]) g_list_out_c[(s*24+cls)*CSTRIDE + sbase[192+s*24+cls] + rout[s]] = v;
        }
        #pragma unroll
        for (int s=0;s<8;s++) out[(s<<18)+v] = 0.f;
        #pragma unroll
        for (int s=0;s<8;s++) {
            bool lab = (s<3) ? (X && g0 && mid==s) : (X && gid==(s-2));
            out[((8+s)<<18)+v] = lab ? 1.f : 0.f;
        }
    } else {
        for (int i=tid;i<432;i+=256) swf[i]=wf1[i];
        if (tid<16) sbf[tid]=bf1[tid];
        __syncthreads();
        int p = (blockIdx.x-1024)*256 + tid;
        if (!g_pocc[p]) return;
        int px=p>>10, py=(p>>5)&31, pz=p&31;
        float acc[16];
        #pragma unroll
        for (int c=0;c<16;c++) acc[c]=sbf[c];
        for (int dx=-1;dx<=1;dx++){ int nx=px+dx; if ((unsigned)nx>=32u) continue;
        for (int dy=-1;dy<=1;dy++){ int ny=py+dy; if ((unsigned)ny>=32u) continue;
        for (int dz=-1;dz<=1;dz++){ int nz=pz+dz; if ((unsigned)nz>=32u) continue;
            if (!g_pocc[(nx<<10)|(ny<<5)|nz]) continue;
            int d = ((dx+1)*3+(dy+1))*3+(dz+1);
            const float* wr = swf + d*16;
            #pragma unroll
            for (int c=0;c<16;c++) acc[c] += wr[c];
        }}}
        float* o = g_h1 + p*16;
        #pragma unroll
        for (int c=0;c<16;c++) o[c] = fmaxf(acc[c],0.f);
    }
}

// ---------------- fused FEL conv2 + upsample (f32x2) ----------------
// Children of unoccupied parents are never read (mask logic guarantees O for all taps).
__global__ void k_fel2up(const float* __restrict__ w, const float* __restrict__ b,
                         const float* __restrict__ wup, const float* __restrict__ bup) {
    __shared__ float sw[27*256];
    __shared__ float su[8*256];
    __shared__ float sb2[16];
    __shared__ float sbu[16];
    int tid = threadIdx.x;
    for (int i=tid;i<6912;i+=256) sw[i]=w[i];
    for (int i=tid;i<2048;i+=256) su[i]=wup[i];
    if (tid<16) { sb2[tid]=b[tid]; sbu[tid]=bup[tid]; }
    __syncthreads();
    int p = blockIdx.x*256 + tid;
    if (!g_pocc[p]) return;
    unsigned long long A[8];
    #pragma unroll
    for (int j=0;j<8;j++) A[j] = pk2(sb2[2*j], sb2[2*j+1]);
    int px=p>>10, py=(p>>5)&31, pz=p&31;
    for (int dx=-1;dx<=1;dx++){ int nx=px+dx; if ((unsigned)nx>=32u) continue;
    for (int dy=-1;dy<=1;dy++){ int ny=py+dy; if ((unsigned)ny>=32u) continue;
    for (int dz=-1;dz<=1;dz++){ int nz=pz+dz; if ((unsigned)nz>=32u) continue;
        int nv = (nx<<10)|(ny<<5)|nz;
        if (!g_pocc[nv]) continue;
        int d = ((dx+1)*3+(dy+1))*3+(dz+1);
        const float4* hp4 = (const float4*)(g_h1 + nv*16);
        float4 h0=hp4[0], h1=hp4[1], h2=hp4[2], h3=hp4[3];
        float in[16] = {h0.x,h0.y,h0.z,h0.w, h1.x,h1.y,h1.z,h1.w,
                        h2.x,h2.y,h2.z,h2.w, h3.x,h3.y,h3.z,h3.w};
        gemv16_f2(A, in, sw + d*256);
    }}}
    float hv[16];
    #pragma unroll
    for (int j=0;j<8;j++) upk2(A[j], hv[2*j], hv[2*j+1]);
    // upsample: 8 children, octant-specific 16x16
    int cx = px<<1, cy = py<<1, cz = pz<<1;
    #pragma unroll
    for (int o=0;o<8;o++) {
        unsigned long long C[8];
        #pragma unroll
        for (int j=0;j<8;j++) C[j] = pk2(sbu[2*j], sbu[2*j+1]);
        gemv16_f2(C, hv, su + o*256);
        int v = ((cx+(o>>2))<<12) | ((cy+((o>>1)&1))<<6) | (cz+(o&1));
        float* pv = g_prob + v*16;
        #pragma unroll
        for (int j=0;j<8;j++) upk2(C[j], pv[2*j], pv[2*j+1]);
    }
}

// ---------------- conv1: 2 voxels/thread, broadcast weights ----------------
__global__ void __launch_bounds__(256) k_conv1_all(K1 P, float* __restrict__ out) {
    int e = blockIdx.x / CH2, ch = blockIdx.x % CH2;
    int s = P.es[e];
    int lid = P.lid[e];
    int cnt = g_cnt_in_c[lid];
    if (ch*512 >= cnt) return;
    __shared__ float sw[6944];
    int tid = threadIdx.x;

    if (s == 0) {
        if (tid < 256) sw[tid] = P.w[0][13*256 + tid];
        if (tid < 16)  sw[6912+tid] = P.w20[13*16 + tid];
        if (tid < 16)  sw[6928+tid] = P.b[0][tid];
        __syncthreads();
        #pragma unroll
        for (int h=0; h<2; h++) {
            int idx = ch*512 + h*256 + tid;
            if (idx >= cnt) break;
            int v = g_list_in_c[lid*CSTRIDE + idx];
            const float4* pin = (const float4*)(g_prob + v*16);
            float4 i0=pin[0], i1=pin[1], i2=pin[2], i3=pin[3];
            float in[16] = {i0.x,i0.y,i0.z,i0.w, i1.x,i1.y,i1.z,i1.w,
                            i2.x,i2.y,i2.z,i2.w, i3.x,i3.y,i3.z,i3.w};
            float a[16];
            #pragma unroll
            for (int c=0;c<16;c++) a[c]=sw[6928+c];
            #pragma unroll
            for (int cin=0;cin<16;cin++){
                float vv = in[cin];
                #pragma unroll
                for (int c=0;c<16;c++) a[c] += vv*sw[cin*16+c];
            }
            float acc = P.b20[0];
            #pragma unroll
            for (int c=0;c<16;c++) acc += fmaxf(a[c],0.f)*sw[6912+c];
            out[v] = 1.f/(1.f + expf(-acc));
        }
        return;
    }

    bool is5 = (s==1 || s==2);
    const float* w = P.w[s];
    if (is5) {
        for (int i=tid;i<6912;i+=256) {
            int t=i>>8, c=i&255;
            int a=t/9, bb=(t/3)%3, cc=t%3;
            sw[i] = w[(((2*a)*5+2*bb)*5+2*cc)*256 + c];
        }
    } else {
        for (int i=tid;i<6912;i+=256) sw[i]=w[i];
    }
    __syncthreads();
    int i0 = ch*512 + tid;
    int i1 = i0 + 256;
    bool ok0 = i0 < cnt, ok1 = i1 < cnt;
    if (!ok0) return;
    int va = g_list_in_c[lid*CSTRIDE + i0];
    int vb = g_list_in_c[lid*CSTRIDE + (ok1 ? i1 : i0)];
    int xa=va>>12, ya=(va>>6)&63, za=va&63;
    int xb=vb>>12, yb=(vb>>6)&63, zb=vb&63;
    int sc = is5 ? 2 : 1;
    unsigned m = P.cand[e];
    const float* bbx = P.b[s];
    float A[16], B[16];
    #pragma unroll
    for (int c=0;c<16;c++) { A[c]=bbx[c]; B[c]=bbx[c]; }
    while (m) {
        int t = __ffs(m)-1; m &= m-1;
        int dx = t/9-1, dy = (t/3)%3-1, dz = t%3-1;
        int nxa=xa+sc*dx, nya=ya+sc*dy, nza=za+sc*dz;
        int nxb=xb+sc*dx, nyb=yb+sc*dy, nzb=zb+sc*dz;
        bool iba = ((unsigned)(nxa|nya|nza) < 64u);
        bool ibb = ((unsigned)(nxb|nyb|nzb) < 64u);
        int nva = ((nxa&63)<<12)|((nya&63)<<6)|(nza&63);
        int nvb = ((nxb&63)<<12)|((nyb&63)<<6)|(nzb&63);
        float sa = (iba && ((g_min[nva]>>s)&1)) ? 1.f : 0.f;
        float sb = (ibb && ((g_min[nvb]>>s)&1)) ? 1.f : 0.f;
        const float4* pa = (const float4*)(g_prob + nva*16);
        const float4* pb = (const float4*)(g_prob + nvb*16);
        float4 a0=pa[0], a1=pa[1], a2=pa[2], a3=pa[3];
        float4 b0=pb[0], b1=pb[1], b2=pb[2], b3=pb[3];
        float ia[16] = {sa*a0.x,sa*a0.y,sa*a0.z,sa*a0.w, sa*a1.x,sa*a1.y,sa*a1.z,sa*a1.w,
                        sa*a2.x,sa*a2.y,sa*a2.z,sa*a2.w, sa*a3.x,sa*a3.y,sa*a3.z,sa*a3.w};
        float ib[16] = {sb*b0.x,sb*b0.y,sb*b0.z,sb*b0.w, sb*b1.x,sb*b1.y,sb*b1.z,sb*b1.w,
                        sb*b2.x,sb*b2.y,sb*b2.z,sb*b2.w, sb*b3.x,sb*b3.y,sb*b3.z,sb*b3.w};
        const float4* pw = (const float4*)(sw + t*256);
        #pragma unroll
        for (int cin=0;cin<16;cin++){
            float u = ia[cin], v2 = ib[cin];
            float4 w0=pw[cin*4+0], w1=pw[cin*4+1], w2=pw[cin*4+2], w3=pw[cin*4+3];
            A[0] += u*w0.x; A[1] += u*w0.y; A[2] += u*w0.z; A[3] += u*w0.w;
            A[4] += u*w1.x; A[5] += u*w1.y; A[6] += u*w1.z; A[7] += u*w1.w;
            A[8] += u*w2.x; A[9] += u*w2.y; A[10]+= u*w2.z; A[11]+= u*w2.w;
            A[12]+= u*w3.x; A[13]+= u*w3.y; A[14]+= u*w3.z; A[15]+= u*w3.w;
            B[0] += v2*w0.x; B[1] += v2*w0.y; B[2] += v2*w0.z; B[3] += v2*w0.w;
            B[4] += v2*w1.x; B[5] += v2*w1.y; B[6] += v2*w1.z; B[7] += v2*w1.w;
            B[8] += v2*w2.x; B[9] += v2*w2.y; B[10]+= v2*w2.z; B[11]+= v2*w2.w;
            B[12]+= v2*w3.x; B[13]+= v2*w3.y; B[14]+= v2*w3.z; B[15]+= v2*w3.w;
        }
    }
    {
        float4* ph = (float4*)(&g_hs[s][va*16]);
        float4 r0 = make_float4(fmaxf(A[0],0.f),fmaxf(A[1],0.f),fmaxf(A[2],0.f),fmaxf(A[3],0.f));
        float4 r1 = make_float4(fmaxf(A[4],0.f),fmaxf(A[5],0.f),fmaxf(A[6],0.f),fmaxf(A[7],0.f));
        float4 r2 = make_float4(fmaxf(A[8],0.f),fmaxf(A[9],0.f),fmaxf(A[10],0.f),fmaxf(A[11],0.f));
        float4 r3 = make_float4(fmaxf(A[12],0.f),fmaxf(A[13],0.f),fmaxf(A[14],0.f),fmaxf(A[15],0.f));
        ph[0]=r0; ph[1]=r1; ph[2]=r2; ph[3]=r3;
    }
    if (ok1) {
        float4* ph = (float4*)(&g_hs[s][vb*16]);
        float4 r0 = make_float4(fmaxf(B[0],0.f),fmaxf(B[1],0.f),fmaxf(B[2],0.f),fmaxf(B[3],0.f));
        float4 r1 = make_float4(fmaxf(B[4],0.f),fmaxf(B[5],0.f),fmaxf(B[6],0.f),fmaxf(B[7],0.f));
        float4 r2 = make_float4(fmaxf(B[8],0.f),fmaxf(B[9],0.f),fmaxf(B[10],0.f),fmaxf(B[11],0.f));
        float4 r3 = make_float4(fmaxf(B[12],0.f),fmaxf(B[13],0.f),fmaxf(B[14],0.f),fmaxf(B[15],0.f));
        ph[0]=r0; ph[1]=r1; ph[2]=r2; ph[3]=r3;
    }
}

// ---------------- conv2: R7 scalar body ----------------
__global__ void __launch_bounds__(256) k_conv2_all(K2 P, float* __restrict__ out) {
    int e = blockIdx.x / CH, ch = blockIdx.x % CH;
    int s = P.es[e];
    int lid = P.lid[e];
    int cnt = g_cnt_out_c[lid];
    if (ch*256 >= cnt) return;
    __shared__ float sw[432];
    int tid = threadIdx.x;
    bool is5 = (s==1 || s==2);
    const float* w = P.w[s];
    if (is5) {
        for (int i=tid;i<432;i+=256) {
            int t=i>>4, c=i&15;
            int a=t/9, bb=(t/3)%3, cc=t%3;
            sw[i] = w[(((2*a)*5+2*bb)*5+2*cc)*16 + c];
        }
    } else {
        for (int i=tid;i<432;i+=256) sw[i]=w[i];
    }
    __syncthreads();
    int idx = ch*256 + tid;
    if (idx >= cnt) return;
    int v = g_list_out_c[lid*CSTRIDE + idx];
    int x=v>>12, y=(v>>6)&63, z=v&63;
    int sc = is5 ? 2 : 1;
    unsigned m = P.cand[e];
    const float* hbase = g_hs[s];
    float acc = P.b[s][0];
    while (m) {
        int t = __ffs(m)-1; m &= m-1;
        int nx = x + sc*(t/9-1), ny = y + sc*((t/3)%3-1), nz = z + sc*(t%3-1);
        bool inb = ((unsigned)(nx|ny|nz) < 64u);
        int nvc = ((nx&63)<<12)|((ny&63)<<6)|(nz&63);
        float sel = (inb && ((g_min[nvc]>>s)&1)) ? 1.f : 0.f;
        const float4* pc = (const float4*)(hbase + nvc*16);
        float4 c0=pc[0], c1=pc[1], c2=pc[2], c3=pc[3];
        const float* wr = sw + t*16;
        float d = c0.x*wr[0] + c0.y*wr[1] + c0.z*wr[2] + c0.w*wr[3]
                + c1.x*wr[4] + c1.y*wr[5] + c1.z*wr[6] + c1.w*wr[7]
                + c2.x*wr[8] + c2.y*wr[9] + c2.z*wr[10]+ c2.w*wr[11]
                + c3.x*wr[12]+ c3.y*wr[13]+ c3.z*wr[14]+ c3.w*wr[15];
        acc += sel*d;
    }
    out[(s<<18)+v] = 1.f/(1.f + expf(-acc));
}

// ---------------- host-side class/LUT construction ----------------
static const int GIDH[8] = {0,5,4,3,4,2,1,5};

static bool cand_in(int s, int par, int mid) {
    int gid = GIDH[par];
    if (s==0) return gid==0 && mid==0;
    if (s==1) return gid==0 && mid<2;
    if (s==2) return gid==0;
    return gid <= s-2;
}

static int middelta(int pc, int d) {
    if (d==-2) return -1;
    if (d== 2) return  1;
    if (d== 0) return  0;
    if (pc==0) return d==-1 ? -1 : 0;
    return d==1 ? 1 : 0;
}

static unsigned mask3(int s, int par, int mid) {
    unsigned m=0;
    for (int t=0;t<27;t++) {
        int dx=t/9-1, dy=(t/3)%3-1, dz=t%3-1;
        int pn = par ^ ((((dx&1))<<2)|(((dy&1))<<1)|(dz&1));
        int dm = middelta((par>>2)&1,dx)+middelta((par>>1)&1,dy)+middelta(par&1,dz);
        int mn = ((mid+dm)%3+3)%3;
        if (cand_in(s,pn,mn)) m |= 1u<<t;
    }
    return m;
}

static unsigned mask5(int s, int mid) {
    unsigned m=0;
    for (int t=0;t<27;t++) {
        int dx=2*(t/9-1), dy=2*((t/3)%3-1), dz=2*(t%3-1);
        int dm=(dx+dy+dz)/2;
        int mn=((mid+dm)%3+3)%3;
        if (cand_in(s,0,mn)) m |= 1u<<t;
    }
    return m;
}

static bool out_class(int s, int par, int mid) {
    int gid = GIDH[par];
    if (s<3) return gid==0 && mid==s;
    return gid == s-2;
}

// ---------------- launch ----------------
extern "C" void kernel_launch(void* const* d_in, const int* in_sizes, int n_in,
                              void* d_out, int out_size) {
    const float* x      = (const float*)d_in[0];
    const float* w_fel1 = (const float*)d_in[3];
    const float* b_fel1 = (const float*)d_in[4];
    const float* w_fel2 = (const float*)d_in[5];
    const float* b_fel2 = (const float*)d_in[6];
    const float* w_up   = (const float*)d_in[7];
    const float* b_up   = (const float*)d_in[8];
    const float* wc1    = (const float*)d_in[9];
    const float* bc1    = (const float*)d_in[10];
    const float* wc2    = (const float*)d_in[11];
    const float* bc2    = (const float*)d_in[12];
    const float* wl1    = (const float*)d_in[13];
    const float* bl1    = (const float*)d_in[14];
    const float* wl2    = (const float*)d_in[15];
    const float* bl2    = (const float*)d_in[16];
    float* out = (float*)d_out;

    K1 p1; K2 p2;
    for (int s=0;s<8;s++) {
        if (s==1 || s==2) {
            p1.w[s] = wl1 + (s-1)*125*256; p1.b[s] = bl1 + (s-1)*16;
            p2.w[s] = wl2 + (s-1)*125*16;  p2.b[s] = bl2 + (s-1);
        } else {
            int k = (s==0) ? 0 : (s-2);
            p1.w[s] = wc1 + k*27*256; p1.b[s] = bc1 + k*16;
            p2.w[s] = wc2 + k*27*16;  p2.b[s] = bc2 + k;
        }
    }
    p1.w20 = wc2; p1.b20 = bc2;

    int n1 = 0;
    for (int s=0;s<8;s++)
        for (int par=0;par<8;par++)
            for (int mid=0;mid<3;mid++)
                if (cand_in(s,par,mid)) {
                    p1.es[n1]  = (unsigned char)s;
                    p1.lid[n1] = s*24 + par*3 + mid;
                    p1.cand[n1] = (s==0) ? (1u<<13)
                                : (s<=2) ? mask5(s,mid)
                                         : mask3(s,par,mid);
                    n1++;
                }
    p1.n_ent = n1;

    int n2 = 0;
    for (int s=1;s<8;s++)
        for (int par=0;par<8;par++)
            for (int mid=0;mid<3;mid++)
                if (out_class(s,par,mid)) {
                    p2.es[n2]  = (unsigned char)s;
                    p2.lid[n2] = s*24 + par*3 + mid;
                    p2.cand[n2] = (s<=2) ? mask5(s,mid) : mask3(s,par,mid);
                    n2++;
                }
    p2.n_ent = n2;

    k_init<<<128,256>>>(x);
    k_maskfel1<<<1152,256>>>(out, w_fel1, b_fel1);
    k_fel2up<<<128,256>>>(w_fel2, b_fel2, w_up, b_up);
    k_conv1_all<<<n1*CH2,256>>>(p1, out);
    k_conv2_all<<<n2*CH,256>>>(p2, out);
}

// round 13
// speedup vs baseline: 3.5808x; 1.1205x over previous
#include <cuda_runtime.h>
#include <math.h>

#define GD 64
#define SD 32
#define NV (GD*GD*GD)
#define NP (SD*SD*SD)

// ---------------- device scratch ----------------
__device__ float g_prob[NV*16];            // PAR-MAJOR: addr = ((par<<15)|parentLin)*16
__device__ float g_hs[8][NV*16];           // par-major per stage
__device__ float g_h1[NP*16];
__device__ unsigned char g_occx[NV];
__device__ unsigned char g_pocc[NP];
__device__ unsigned char g_minp[NV];       // par-major in-mask bits
__device__ unsigned char g_moutp[NV];      // par-major out-mask bits

struct K1 {
    const float* w[8]; const float* b[8];
    const float* w20; const float* b20;
    int n_ent;
    unsigned cand[26]; unsigned char es[26]; unsigned char par[26];
};
struct K2 {
    const float* w[8]; const float* b[8];
    int n_ent;
    unsigned cand[9]; unsigned char es[9]; unsigned char par[9];
};

// ---------------- packed f32x2 helpers ----------------
__device__ __forceinline__ unsigned long long pk2(float lo, float hi) {
    unsigned long long r;
    asm("mov.b64 %0, {%1, %2};" : "=l"(r) : "f"(lo), "f"(hi));
    return r;
}
__device__ __forceinline__ unsigned long long pk2(float v) { return pk2(v, v); }
__device__ __forceinline__ void upk2(unsigned long long v, float& lo, float& hi) {
    asm("mov.b64 {%0, %1}, %2;" : "=f"(lo), "=f"(hi) : "l"(v));
}
__device__ __forceinline__ void f2fma(unsigned long long& d, unsigned long long a, unsigned long long b) {
    asm("fma.rn.f32x2 %0, %1, %2, %0;" : "+l"(d) : "l"(a), "l"(b));
}
__device__ __forceinline__ void gemv16_f2(unsigned long long* A, const float* in,
                                          const float* wrow) {
    const ulonglong2* wp = (const ulonglong2*)wrow;
    #pragma unroll
    for (int cin=0; cin<16; cin++) {
        unsigned long long v2 = pk2(in[cin]);
        ulonglong2 w01 = wp[cin*4+0];
        ulonglong2 w23 = wp[cin*4+1];
        ulonglong2 w45 = wp[cin*4+2];
        ulonglong2 w67 = wp[cin*4+3];
        f2fma(A[0], v2, w01.x); f2fma(A[1], v2, w01.y);
        f2fma(A[2], v2, w23.x); f2fma(A[3], v2, w23.y);
        f2fma(A[4], v2, w45.x); f2fma(A[5], v2, w45.y);
        f2fma(A[6], v2, w67.x); f2fma(A[7], v2, w67.y);
    }
}

// ---------------- init: occ + pocc ----------------
__global__ void k_init(const float* __restrict__ x) {
    int p = blockIdx.x*256 + threadIdx.x;
    if (p >= NP) return;
    int px = p>>10, py = (p>>5)&31, pz = p&31;
    int bx = px<<1, by = py<<1, bz = pz<<1;
    unsigned char o = 0;
    #pragma unroll
    for (int a=0;a<2;a++)
    #pragma unroll
    for (int b=0;b<2;b++)
    #pragma unroll
    for (int c=0;c<2;c++) {
        int v = ((bx+a)<<12)|((by+b)<<6)|(bz+c);
        unsigned char oc = (x[v] > 0.f) ? 1 : 0;
        g_occx[v] = oc;
        o |= oc;
    }
    g_pocc[p] = o;
}

// ---------------- fused: masks (par-major) + labels + FEL conv1 ----------------
__global__ void k_maskfel1(float* __restrict__ out,
                           const float* __restrict__ wf1, const float* __restrict__ bf1) {
    __shared__ float swf[432];
    __shared__ float sbf[16];
    int tid = threadIdx.x;
    if (blockIdx.x < 1024) {
        int v = blockIdx.x*256 + tid;
        int x = v>>12, y = (v>>6)&63, z = v&63;
        const int LUT[8] = {0,5,4,3,4,2,1,5};
        int par = ((x&1)<<2)|((y&1)<<1)|(z&1);
        int gid = LUT[par];
        int mid = ((x>>1)+(y>>1)+(z>>1)) % 3;
        bool O = g_pocc[((x>>1)<<10)|((y>>1)<<5)|(z>>1)] != 0;
        bool X = g_occx[v] != 0;
        bool g0 = (gid == 0);

        bool bi[8], bo[8];
        bi[0] = O && g0 && (mid==0);
        bi[1] = (O && g0 && mid==1) || (X && g0 && mid==0);
        bi[2] = (X && g0 && mid<2)  || (O && g0 && mid==2);
        bi[3] = (X && g0)      || (O && gid==1);
        bi[4] = (X && gid<=1)  || (O && gid==2);
        bi[5] = (X && gid<=2)  || (O && gid==3);
        bi[6] = (X && gid<=3)  || (O && gid==4);
        bi[7] = (X && gid<=4)  || (O && gid==5);
        bo[0] = O && g0 && mid==0;
        bo[1] = O && g0 && mid==1;
        bo[2] = O && g0 && mid==2;
        #pragma unroll
        for (int s=3;s<8;s++) bo[s] = O && (gid == s-2);

        unsigned char mb = 0, mo = 0;
        #pragma unroll
        for (int s=0;s<8;s++) {
            if (bi[s]) mb |= (1u<<s);
            if (bo[s]) mo |= (1u<<s);
        }
        int pm = (par<<15) | ((x>>1)<<10) | ((y>>1)<<5) | (z>>1);
        g_minp[pm]  = mb;
        g_moutp[pm] = mo;
        #pragma unroll
        for (int s=0;s<8;s++) out[(s<<18)+v] = 0.f;
        #pragma unroll
        for (int s=0;s<8;s++) {
            bool lab = (s<3) ? (X && g0 && mid==s) : (X && gid==(s-2));
            out[((8+s)<<18)+v] = lab ? 1.f : 0.f;
        }
    } else {
        for (int i=tid;i<432;i+=256) swf[i]=wf1[i];
        if (tid<16) sbf[tid]=bf1[tid];
        __syncthreads();
        int p = (blockIdx.x-1024)*256 + tid;
        if (!g_pocc[p]) return;
        int px=p>>10, py=(p>>5)&31, pz=p&31;
        float acc[16];
        #pragma unroll
        for (int c=0;c<16;c++) acc[c]=sbf[c];
        for (int dx=-1;dx<=1;dx++){ int nx=px+dx; if ((unsigned)nx>=32u) continue;
        for (int dy=-1;dy<=1;dy++){ int ny=py+dy; if ((unsigned)ny>=32u) continue;
        for (int dz=-1;dz<=1;dz++){ int nz=pz+dz; if ((unsigned)nz>=32u) continue;
            if (!g_pocc[(nx<<10)|(ny<<5)|nz]) continue;
            int d = ((dx+1)*3+(dy+1))*3+(dz+1);
            const float* wr = swf + d*16;
            #pragma unroll
            for (int c=0;c<16;c++) acc[c] += wr[c];
        }}}
        float* o = g_h1 + p*16;
        #pragma unroll
        for (int c=0;c<16;c++) o[c] = fmaxf(acc[c],0.f);
    }
}

// ---------------- fused FEL conv2 + upsample -> par-major prob ----------------
__global__ void k_fel2up(const float* __restrict__ w, const float* __restrict__ b,
                         const float* __restrict__ wup, const float* __restrict__ bup) {
    __shared__ float sw[27*256];
    __shared__ float su[8*256];
    __shared__ float sb2[16];
    __shared__ float sbu[16];
    int tid = threadIdx.x;
    for (int i=tid;i<6912;i+=256) sw[i]=w[i];
    for (int i=tid;i<2048;i+=256) su[i]=wup[i];
    if (tid<16) { sb2[tid]=b[tid]; sbu[tid]=bup[tid]; }
    __syncthreads();
    int p = blockIdx.x*256 + tid;
    if (!g_pocc[p]) return;
    unsigned long long A[8];
    #pragma unroll
    for (int j=0;j<8;j++) A[j] = pk2(sb2[2*j], sb2[2*j+1]);
    int px=p>>10, py=(p>>5)&31, pz=p&31;
    for (int dx=-1;dx<=1;dx++){ int nx=px+dx; if ((unsigned)nx>=32u) continue;
    for (int dy=-1;dy<=1;dy++){ int ny=py+dy; if ((unsigned)ny>=32u) continue;
    for (int dz=-1;dz<=1;dz++){ int nz=pz+dz; if ((unsigned)nz>=32u) continue;
        int nv = (nx<<10)|(ny<<5)|nz;
        if (!g_pocc[nv]) continue;
        int d = ((dx+1)*3+(dy+1))*3+(dz+1);
        const float4* hp4 = (const float4*)(g_h1 + nv*16);
        float4 h0=hp4[0], h1=hp4[1], h2=hp4[2], h3=hp4[3];
        float in[16] = {h0.x,h0.y,h0.z,h0.w, h1.x,h1.y,h1.z,h1.w,
                        h2.x,h2.y,h2.z,h2.w, h3.x,h3.y,h3.z,h3.w};
        gemv16_f2(A, in, sw + d*256);
    }}}
    float hv[16];
    #pragma unroll
    for (int j=0;j<8;j++) upk2(A[j], hv[2*j], hv[2*j+1]);
    #pragma unroll
    for (int o=0;o<8;o++) {
        unsigned long long C[8];
        #pragma unroll
        for (int j=0;j<8;j++) C[j] = pk2(sbu[2*j], sbu[2*j+1]);
        gemv16_f2(C, hv, su + o*256);
        float* pv = g_prob + ((o<<15)|p)*16;     // par-major, contiguous per octant
        #pragma unroll
        for (int j=0;j<8;j++) upk2(C[j], pv[2*j], pv[2*j+1]);
    }
}

// ---------------- conv1: dense par-major, 2 voxels/thread ----------------
__global__ void __launch_bounds__(256) k_conv1_all(K1 P, float* __restrict__ out) {
    int e = blockIdx.x >> 6, ch = blockIdx.x & 63;
    int s = P.es[e];
    int par = P.par[e];
    __shared__ float sw[6944];
    int tid = threadIdx.x;
    int ox = (par>>2)&1, oy = (par>>1)&1, oz = par&1;

    if (s == 0) {
        if (tid < 256) sw[tid] = P.w[0][13*256 + tid];
        if (tid < 16)  sw[6912+tid] = P.w20[13*16 + tid];
        if (tid < 16)  sw[6928+tid] = P.b[0][tid];
        __syncthreads();
        #pragma unroll
        for (int h=0; h<2; h++) {
            int pi = ch*512 + h*256 + tid;
            if (!(g_minp[pi] & 1)) continue;         // par0: pm == pi
            const float4* pin = (const float4*)(g_prob + pi*16);
            float4 i0=pin[0], i1=pin[1], i2=pin[2], i3=pin[3];
            float in[16] = {i0.x,i0.y,i0.z,i0.w, i1.x,i1.y,i1.z,i1.w,
                            i2.x,i2.y,i2.z,i2.w, i3.x,i3.y,i3.z,i3.w};
            float a[16];
            #pragma unroll
            for (int c=0;c<16;c++) a[c]=sw[6928+c];
            #pragma unroll
            for (int cin=0;cin<16;cin++){
                float vv = in[cin];
                #pragma unroll
                for (int c=0;c<16;c++) a[c] += vv*sw[cin*16+c];
            }
            float acc = P.b20[0];
            #pragma unroll
            for (int c=0;c<16;c++) acc += fmaxf(a[c],0.f)*sw[6912+c];
            int xv = ((pi>>10)<<1), yv = (((pi>>5)&31)<<1), zv = ((pi&31)<<1);
            out[(xv<<12)|(yv<<6)|zv] = 1.f/(1.f + expf(-acc));
        }
        return;
    }

    bool is5 = (s==1 || s==2);
    const float* w = P.w[s];
    if (is5) {
        for (int i=tid;i<6912;i+=256) {
            int t=i>>8, c=i&255;
            int a=t/9, bb=(t/3)%3, cc=t%3;
            sw[i] = w[(((2*a)*5+2*bb)*5+2*cc)*256 + c];
        }
    } else {
        for (int i=tid;i<6912;i+=256) sw[i]=w[i];
    }
    __syncthreads();
    int pia = ch*512 + tid;
    int pib = pia + 256;
    int xa = ((pia>>10)<<1)|ox, ya = (((pia>>5)&31)<<1)|oy, za = ((pia&31)<<1)|oz;
    int yb = ya + 16;                              // pib differs only in b (+8)
    int sc = is5 ? 2 : 1;
    unsigned m = P.cand[e];
    const float* bbx = P.b[s];
    float A[16], B[16];
    #pragma unroll
    for (int c=0;c<16;c++) { A[c]=bbx[c]; B[c]=bbx[c]; }
    while (m) {
        int t = __ffs(m)-1; m &= m-1;
        int dx = sc*(t/9-1), dy = sc*((t/3)%3-1), dz = sc*(t%3-1);
        int nxa=xa+dx, nya=ya+dy, nza=za+dz;
        int nyb=yb+dy;
        bool iba = ((unsigned)(nxa|nya|nza) < 64u);
        bool ibb = ((unsigned)(nxa|nyb|nza) < 64u);
        int ma=nxa&63, mya=nya&63, mza=nza&63, myb=nyb&63;
        int npp = ((((ma&1)<<2)|((mza&1)))|((mya&1)<<1))<<15;
        int base = ((ma>>1)<<10) | (mza>>1);
        int npa = npp | base | ((mya>>1)<<5);
        int npb = npp | base | ((myb>>1)<<5);
        float sa = (iba && ((g_minp[npa]>>s)&1)) ? 1.f : 0.f;
        float sb = (ibb && ((g_minp[npb]>>s)&1)) ? 1.f : 0.f;
        const float4* pa4 = (const float4*)(g_prob + npa*16);
        const float4* pb4 = (const float4*)(g_prob + npb*16);
        const float4* pw = (const float4*)(sw + t*256);
        #pragma unroll
        for (int q4=0;q4<4;q4++){
            float4 ua = pa4[q4];
            float4 ub = pb4[q4];
            ua.x*=sa; ua.y*=sa; ua.z*=sa; ua.w*=sa;
            ub.x*=sb; ub.y*=sb; ub.z*=sb; ub.w*=sb;
            #pragma unroll
            for (int k=0;k<4;k++){
                float u = (&ua.x)[k], v2 = (&ub.x)[k];
                float4 w0=pw[(q4*4+k)*4+0], w1=pw[(q4*4+k)*4+1],
                       w2=pw[(q4*4+k)*4+2], w3=pw[(q4*4+k)*4+3];
                A[0]+=u*w0.x; A[1]+=u*w0.y; A[2]+=u*w0.z; A[3]+=u*w0.w;
                A[4]+=u*w1.x; A[5]+=u*w1.y; A[6]+=u*w1.z; A[7]+=u*w1.w;
                A[8]+=u*w2.x; A[9]+=u*w2.y; A[10]+=u*w2.z; A[11]+=u*w2.w;
                A[12]+=u*w3.x; A[13]+=u*w3.y; A[14]+=u*w3.z; A[15]+=u*w3.w;
                B[0]+=v2*w0.x; B[1]+=v2*w0.y; B[2]+=v2*w0.z; B[3]+=v2*w0.w;
                B[4]+=v2*w1.x; B[5]+=v2*w1.y; B[6]+=v2*w1.z; B[7]+=v2*w1.w;
                B[8]+=v2*w2.x; B[9]+=v2*w2.y; B[10]+=v2*w2.z; B[11]+=v2*w2.w;
                B[12]+=v2*w3.x; B[13]+=v2*w3.y; B[14]+=v2*w3.z; B[15]+=v2*w3.w;
            }
        }
    }
    {
        float4* ph = (float4*)(&g_hs[s][((par<<15)|pia)*16]);
        ph[0]=make_float4(fmaxf(A[0],0.f),fmaxf(A[1],0.f),fmaxf(A[2],0.f),fmaxf(A[3],0.f));
        ph[1]=make_float4(fmaxf(A[4],0.f),fmaxf(A[5],0.f),fmaxf(A[6],0.f),fmaxf(A[7],0.f));
        ph[2]=make_float4(fmaxf(A[8],0.f),fmaxf(A[9],0.f),fmaxf(A[10],0.f),fmaxf(A[11],0.f));
        ph[3]=make_float4(fmaxf(A[12],0.f),fmaxf(A[13],0.f),fmaxf(A[14],0.f),fmaxf(A[15],0.f));
    }
    {
        float4* ph = (float4*)(&g_hs[s][((par<<15)|pib)*16]);
        ph[0]=make_float4(fmaxf(B[0],0.f),fmaxf(B[1],0.f),fmaxf(B[2],0.f),fmaxf(B[3],0.f));
        ph[1]=make_float4(fmaxf(B[4],0.f),fmaxf(B[5],0.f),fmaxf(B[6],0.f),fmaxf(B[7],0.f));
        ph[2]=make_float4(fmaxf(B[8],0.f),fmaxf(B[9],0.f),fmaxf(B[10],0.f),fmaxf(B[11],0.f));
        ph[3]=make_float4(fmaxf(B[12],0.f),fmaxf(B[13],0.f),fmaxf(B[14],0.f),fmaxf(B[15],0.f));
    }
}

// ---------------- conv2: dense par-major ----------------
__global__ void __launch_bounds__(256) k_conv2_all(K2 P, float* __restrict__ out) {
    int e = blockIdx.x >> 7, ch = blockIdx.x & 127;
    int s = P.es[e];
    int par = P.par[e];
    __shared__ float sw[432];
    int tid = threadIdx.x;
    bool is5 = (s==1 || s==2);
    const float* w = P.w[s];
    if (is5) {
        for (int i=tid;i<432;i+=256) {
            int t=i>>4, c=i&15;
            int a=t/9, bb=(t/3)%3, cc=t%3;
            sw[i] = w[(((2*a)*5+2*bb)*5+2*cc)*16 + c];
        }
    } else {
        for (int i=tid;i<432;i+=256) sw[i]=w[i];
    }
    __syncthreads();
    int pi = ch*256 + tid;
    int pm = (par<<15)|pi;
    if (!((g_moutp[pm]>>s)&1)) return;
    int ox = (par>>2)&1, oy = (par>>1)&1, oz = par&1;
    int x = ((pi>>10)<<1)|ox, y = (((pi>>5)&31)<<1)|oy, z = ((pi&31)<<1)|oz;
    int sc = is5 ? 2 : 1;
    unsigned m = P.cand[e];
    const float* hbase = g_hs[s];
    float acc = P.b[s][0];
    while (m) {
        int t = __ffs(m)-1; m &= m-1;
        int nx = x + sc*(t/9-1), ny = y + sc*((t/3)%3-1), nz = z + sc*(t%3-1);
        bool inb = ((unsigned)(nx|ny|nz) < 64u);
        int mx=nx&63, my=ny&63, mz=nz&63;
        int npm = ((((mx&1)<<2)|((my&1)<<1)|(mz&1))<<15) | ((mx>>1)<<10)|((my>>1)<<5)|(mz>>1);
        float sel = (inb && ((g_minp[npm]>>s)&1)) ? 1.f : 0.f;
        const float4* pc = (const float4*)(hbase + npm*16);
        float4 c0=pc[0], c1=pc[1], c2=pc[2], c3=pc[3];
        const float* wr = sw + t*16;
        float d = c0.x*wr[0] + c0.y*wr[1] + c0.z*wr[2] + c0.w*wr[3]
                + c1.x*wr[4] + c1.y*wr[5] + c1.z*wr[6] + c1.w*wr[7]
                + c2.x*wr[8] + c2.y*wr[9] + c2.z*wr[10]+ c2.w*wr[11]
                + c3.x*wr[12]+ c3.y*wr[13]+ c3.z*wr[14]+ c3.w*wr[15];
        acc += sel*d;
    }
    out[(s<<18) | (x<<12)|(y<<6)|z] = 1.f/(1.f + expf(-acc));
}

// ---------------- host-side construction ----------------
static const int GIDH[8] = {0,5,4,3,4,2,1,5};

static unsigned mask3(int s, int par) {
    // s>=3: candidate iff gid(target parity) <= s-2 (mid-independent)
    unsigned m=0;
    for (int t=0;t<27;t++) {
        int dx=t/9-1, dy=(t/3)%3-1, dz=t%3-1;
        int pn = par ^ ((((dx&1))<<2)|(((dy&1))<<1)|(dz&1));
        if (GIDH[pn] <= s-2) m |= 1u<<t;
    }
    return m;
}

// ---------------- launch ----------------
extern "C" void kernel_launch(void* const* d_in, const int* in_sizes, int n_in,
                              void* d_out, int out_size) {
    const float* x      = (const float*)d_in[0];
    const float* w_fel1 = (const float*)d_in[3];
    const float* b_fel1 = (const float*)d_in[4];
    const float* w_fel2 = (const float*)d_in[5];
    const float* b_fel2 = (const float*)d_in[6];
    const float* w_up   = (const float*)d_in[7];
    const float* b_up   = (const float*)d_in[8];
    const float* wc1    = (const float*)d_in[9];
    const float* bc1    = (const float*)d_in[10];
    const float* wc2    = (const float*)d_in[11];
    const float* bc2    = (const float*)d_in[12];
    const float* wl1    = (const float*)d_in[13];
    const float* bl1    = (const float*)d_in[14];
    const float* wl2    = (const float*)d_in[15];
    const float* bl2    = (const float*)d_in[16];
    float* out = (float*)d_out;

    K1 p1; K2 p2;
    for (int s=0;s<8;s++) {
        if (s==1 || s==2) {
            p1.w[s] = wl1 + (s-1)*125*256; p1.b[s] = bl1 + (s-1)*16;
            p2.w[s] = wl2 + (s-1)*125*16;  p2.b[s] = bl2 + (s-1);
        } else {
            int k = (s==0) ? 0 : (s-2);
            p1.w[s] = wc1 + k*27*256; p1.b[s] = bc1 + k*16;
            p2.w[s] = wc2 + k*27*16;  p2.b[s] = bc2 + k;
        }
    }
    p1.w20 = wc2; p1.b20 = bc2;

    // conv1 entries: (stage, parity) lattices
    int n1 = 0;
    for (int s=0;s<8;s++)
        for (int par=0;par<8;par++) {
            bool incl = (s<=2) ? (par==0) : (GIDH[par] <= s-2);
            if (!incl) continue;
            p1.es[n1]  = (unsigned char)s;
            p1.par[n1] = (unsigned char)par;
            p1.cand[n1] = (s==0) ? (1u<<13)
                        : (s<=2) ? 0x07FFFFFFu
                                 : mask3(s,par);
            n1++;
        }
    p1.n_ent = n1;

    // conv2 entries: output parities per stage
    int n2 = 0;
    for (int s=1;s<8;s++)
        for (int par=0;par<8;par++) {
            bool incl = (s<=2) ? (par==0) : (GIDH[par] == s-2);
            if (!incl) continue;
            p2.es[n2]  = (unsigned char)s;
            p2.par[n2] = (unsigned char)par;
            p2.cand[n2] = (s<=2) ? 0x07FFFFFFu : mask3(s,par);
            n2++;
        }
    p2.n_ent = n2;

    k_init<<<128,256>>>(x);
    k_maskfel1<<<1152,256>>>(out, w_fel1, b_fel1);
    k_fel2up<<<128,256>>>(w_fel2, b_fel2, w_up, b_up);
    k_conv1_all<<<n1*64,256>>>(p1, out);
    k_conv2_all<<<n2*128,256>>>(p2, out);
}

// round 14
// speedup vs baseline: 3.9260x; 1.0964x over previous
#include <cuda_runtime.h>
#include <math.h>

#define GD 64
#define SD 32
#define NV (GD*GD*GD)
#define NP (SD*SD*SD)

// ---------------- device scratch ----------------
__device__ float g_prob[NV*16];            // PAR-MAJOR: addr = ((par<<15)|parentLin)*16
__device__ float g_hs[8][NV*16];           // par-major per stage
__device__ float g_h1[NP*16];
__device__ unsigned char g_occx[NV];
__device__ unsigned char g_pocc[NP];
__device__ unsigned char g_minp[NV];       // par-major in-mask bits
__device__ unsigned char g_moutp[NV];      // par-major out-mask bits

struct K1 {
    const float* w[8]; const float* b[8];
    const float* w20; const float* b20;
    int n_ent;
    unsigned cand[26]; unsigned char es[26]; unsigned char par[26];
};
struct K2 {
    const float* w[8]; const float* b[8];
    int n_ent;
    unsigned cand[9]; unsigned char es[9]; unsigned char par[9];
};

// ---------------- packed f32x2 helpers ----------------
__device__ __forceinline__ unsigned long long pk2(float lo, float hi) {
    unsigned long long r;
    asm("mov.b64 %0, {%1, %2};" : "=l"(r) : "f"(lo), "f"(hi));
    return r;
}
__device__ __forceinline__ unsigned long long pk2(float v) { return pk2(v, v); }
__device__ __forceinline__ void upk2(unsigned long long v, float& lo, float& hi) {
    asm("mov.b64 {%0, %1}, %2;" : "=f"(lo), "=f"(hi) : "l"(v));
}
__device__ __forceinline__ void f2fma(unsigned long long& d, unsigned long long a, unsigned long long b) {
    asm("fma.rn.f32x2 %0, %1, %2, %0;" : "+l"(d) : "l"(a), "l"(b));
}
__device__ __forceinline__ void gemv16_f2(unsigned long long* A, const float* in,
                                          const float* wrow) {
    const ulonglong2* wp = (const ulonglong2*)wrow;
    #pragma unroll
    for (int cin=0; cin<16; cin++) {
        unsigned long long v2 = pk2(in[cin]);
        ulonglong2 w01 = wp[cin*4+0];
        ulonglong2 w23 = wp[cin*4+1];
        ulonglong2 w45 = wp[cin*4+2];
        ulonglong2 w67 = wp[cin*4+3];
        f2fma(A[0], v2, w01.x); f2fma(A[1], v2, w01.y);
        f2fma(A[2], v2, w23.x); f2fma(A[3], v2, w23.y);
        f2fma(A[4], v2, w45.x); f2fma(A[5], v2, w45.y);
        f2fma(A[6], v2, w67.x); f2fma(A[7], v2, w67.y);
    }
}

// ---------------- init: occ + pocc ----------------
__global__ void k_init(const float* __restrict__ x) {
    int p = blockIdx.x*256 + threadIdx.x;
    if (p >= NP) return;
    int px = p>>10, py = (p>>5)&31, pz = p&31;
    int bx = px<<1, by = py<<1, bz = pz<<1;
    unsigned char o = 0;
    #pragma unroll
    for (int a=0;a<2;a++)
    #pragma unroll
    for (int b=0;b<2;b++)
    #pragma unroll
    for (int c=0;c<2;c++) {
        int v = ((bx+a)<<12)|((by+b)<<6)|(bz+c);
        unsigned char oc = (x[v] > 0.f) ? 1 : 0;
        g_occx[v] = oc;
        o |= oc;
    }
    g_pocc[p] = o;
}

// ---------------- fused: masks (par-major) + labels + FEL conv1 ----------------
__global__ void k_maskfel1(float* __restrict__ out,
                           const float* __restrict__ wf1, const float* __restrict__ bf1) {
    __shared__ float swf[432];
    __shared__ float sbf[16];
    int tid = threadIdx.x;
    if (blockIdx.x < 1024) {
        int v = blockIdx.x*256 + tid;
        int x = v>>12, y = (v>>6)&63, z = v&63;
        const int LUT[8] = {0,5,4,3,4,2,1,5};
        int par = ((x&1)<<2)|((y&1)<<1)|(z&1);
        int gid = LUT[par];
        int mid = ((x>>1)+(y>>1)+(z>>1)) % 3;
        bool O = g_pocc[((x>>1)<<10)|((y>>1)<<5)|(z>>1)] != 0;
        bool X = g_occx[v] != 0;
        bool g0 = (gid == 0);

        bool bi[8], bo[8];
        bi[0] = O && g0 && (mid==0);
        bi[1] = (O && g0 && mid==1) || (X && g0 && mid==0);
        bi[2] = (X && g0 && mid<2)  || (O && g0 && mid==2);
        bi[3] = (X && g0)      || (O && gid==1);
        bi[4] = (X && gid<=1)  || (O && gid==2);
        bi[5] = (X && gid<=2)  || (O && gid==3);
        bi[6] = (X && gid<=3)  || (O && gid==4);
        bi[7] = (X && gid<=4)  || (O && gid==5);
        bo[0] = O && g0 && mid==0;
        bo[1] = O && g0 && mid==1;
        bo[2] = O && g0 && mid==2;
        #pragma unroll
        for (int s=3;s<8;s++) bo[s] = O && (gid == s-2);

        unsigned char mb = 0, mo = 0;
        #pragma unroll
        for (int s=0;s<8;s++) {
            if (bi[s]) mb |= (1u<<s);
            if (bo[s]) mo |= (1u<<s);
        }
        int pm = (par<<15) | ((x>>1)<<10) | ((y>>1)<<5) | (z>>1);
        g_minp[pm]  = mb;
        g_moutp[pm] = mo;
        #pragma unroll
        for (int s=0;s<8;s++) out[(s<<18)+v] = 0.f;
        #pragma unroll
        for (int s=0;s<8;s++) {
            bool lab = (s<3) ? (X && g0 && mid==s) : (X && gid==(s-2));
            out[((8+s)<<18)+v] = lab ? 1.f : 0.f;
        }
    } else {
        for (int i=tid;i<432;i+=256) swf[i]=wf1[i];
        if (tid<16) sbf[tid]=bf1[tid];
        __syncthreads();
        int p = (blockIdx.x-1024)*256 + tid;
        if (!g_pocc[p]) return;
        int px=p>>10, py=(p>>5)&31, pz=p&31;
        float acc[16];
        #pragma unroll
        for (int c=0;c<16;c++) acc[c]=sbf[c];
        for (int dx=-1;dx<=1;dx++){ int nx=px+dx; if ((unsigned)nx>=32u) continue;
        for (int dy=-1;dy<=1;dy++){ int ny=py+dy; if ((unsigned)ny>=32u) continue;
        for (int dz=-1;dz<=1;dz++){ int nz=pz+dz; if ((unsigned)nz>=32u) continue;
            if (!g_pocc[(nx<<10)|(ny<<5)|nz]) continue;
            int d = ((dx+1)*3+(dy+1))*3+(dz+1);
            const float* wr = swf + d*16;
            #pragma unroll
            for (int c=0;c<16;c++) acc[c] += wr[c];
        }}}
        float* o = g_h1 + p*16;
        #pragma unroll
        for (int c=0;c<16;c++) o[c] = fmaxf(acc[c],0.f);
    }
}

// ---------------- fused FEL conv2 + upsample -> par-major prob ----------------
__global__ void k_fel2up(const float* __restrict__ w, const float* __restrict__ b,
                         const float* __restrict__ wup, const float* __restrict__ bup) {
    __shared__ float sw[27*256];
    __shared__ float su[8*256];
    __shared__ float sb2[16];
    __shared__ float sbu[16];
    int tid = threadIdx.x;
    for (int i=tid;i<6912;i+=256) sw[i]=w[i];
    for (int i=tid;i<2048;i+=256) su[i]=wup[i];
    if (tid<16) { sb2[tid]=b[tid]; sbu[tid]=bup[tid]; }
    __syncthreads();
    int p = blockIdx.x*256 + tid;
    if (!g_pocc[p]) return;
    unsigned long long A[8];
    #pragma unroll
    for (int j=0;j<8;j++) A[j] = pk2(sb2[2*j], sb2[2*j+1]);
    int px=p>>10, py=(p>>5)&31, pz=p&31;
    for (int dx=-1;dx<=1;dx++){ int nx=px+dx; if ((unsigned)nx>=32u) continue;
    for (int dy=-1;dy<=1;dy++){ int ny=py+dy; if ((unsigned)ny>=32u) continue;
    for (int dz=-1;dz<=1;dz++){ int nz=pz+dz; if ((unsigned)nz>=32u) continue;
        int nv = (nx<<10)|(ny<<5)|nz;
        if (!g_pocc[nv]) continue;
        int d = ((dx+1)*3+(dy+1))*3+(dz+1);
        const float4* hp4 = (const float4*)(g_h1 + nv*16);
        float4 h0=hp4[0], h1=hp4[1], h2=hp4[2], h3=hp4[3];
        float in[16] = {h0.x,h0.y,h0.z,h0.w, h1.x,h1.y,h1.z,h1.w,
                        h2.x,h2.y,h2.z,h2.w, h3.x,h3.y,h3.z,h3.w};
        gemv16_f2(A, in, sw + d*256);
    }}}
    float hv[16];
    #pragma unroll
    for (int j=0;j<8;j++) upk2(A[j], hv[2*j], hv[2*j+1]);
    #pragma unroll
    for (int o=0;o<8;o++) {
        unsigned long long C[8];
        #pragma unroll
        for (int j=0;j<8;j++) C[j] = pk2(sbu[2*j], sbu[2*j+1]);
        gemv16_f2(C, hv, su + o*256);
        float* pv = g_prob + ((o<<15)|p)*16;
        #pragma unroll
        for (int j=0;j<8;j++) upk2(C[j], pv[2*j], pv[2*j+1]);
    }
}

// ---------------- conv1: dense par-major, 4 voxels/thread ----------------
__global__ void __launch_bounds__(256) k_conv1_all(K1 P, float* __restrict__ out) {
    int e = blockIdx.x >> 5, ch = blockIdx.x & 31;
    int s = P.es[e];
    int par = P.par[e];
    __shared__ float sw[6944];
    int tid = threadIdx.x;
    int ox = (par>>2)&1, oy = (par>>1)&1, oz = par&1;

    if (s == 0) {
        if (tid < 256) sw[tid] = P.w[0][13*256 + tid];
        if (tid < 16)  sw[6912+tid] = P.w20[13*16 + tid];
        if (tid < 16)  sw[6928+tid] = P.b[0][tid];
        __syncthreads();
        #pragma unroll
        for (int h=0; h<4; h++) {
            int pi = ch*1024 + h*256 + tid;
            if (!(g_minp[pi] & 1)) continue;
            const float4* pin = (const float4*)(g_prob + pi*16);
            float4 i0=pin[0], i1=pin[1], i2=pin[2], i3=pin[3];
            float in[16] = {i0.x,i0.y,i0.z,i0.w, i1.x,i1.y,i1.z,i1.w,
                            i2.x,i2.y,i2.z,i2.w, i3.x,i3.y,i3.z,i3.w};
            float a[16];
            #pragma unroll
            for (int c=0;c<16;c++) a[c]=sw[6928+c];
            #pragma unroll
            for (int cin=0;cin<16;cin++){
                float vv = in[cin];
                #pragma unroll
                for (int c=0;c<16;c++) a[c] += vv*sw[cin*16+c];
            }
            float acc = P.b20[0];
            #pragma unroll
            for (int c=0;c<16;c++) acc += fmaxf(a[c],0.f)*sw[6912+c];
            int xv = ((pi>>10)<<1), yv = (((pi>>5)&31)<<1), zv = ((pi&31)<<1);
            out[(xv<<12)|(yv<<6)|zv] = 1.f/(1.f + expf(-acc));
        }
        return;
    }

    bool is5 = (s==1 || s==2);
    const float* w = P.w[s];
    if (is5) {
        for (int i=tid;i<6912;i+=256) {
            int t=i>>8, c=i&255;
            int a=t/9, bb=(t/3)%3, cc=t%3;
            sw[i] = w[(((2*a)*5+2*bb)*5+2*cc)*256 + c];
        }
    } else {
        for (int i=tid;i<6912;i+=256) sw[i]=w[i];
    }
    __syncthreads();
    int pi0 = ch*1024 + tid;                       // voxels: pi0, +256, +512, +768 (y += 16 each)
    int xa = ((pi0>>10)<<1)|ox, ya = (((pi0>>5)&31)<<1)|oy, za = ((pi0&31)<<1)|oz;
    int sc = is5 ? 2 : 1;
    unsigned m = P.cand[e];
    const float* bbx = P.b[s];
    float A0[16], A1[16], A2[16], A3[16];
    #pragma unroll
    for (int c=0;c<16;c++) { A0[c]=bbx[c]; A1[c]=bbx[c]; A2[c]=bbx[c]; A3[c]=bbx[c]; }
    while (m) {
        int t = __ffs(m)-1; m &= m-1;
        int dx = sc*(t/9-1), dy = sc*((t/3)%3-1), dz = sc*(t%3-1);
        int nx=xa+dx, nz=za+dz;
        int ny0=ya+dy, ny1=ny0+16, ny2=ny0+32, ny3=ny0+48;
        int mx=nx&63, mz=nz&63;
        bool ib0 = ((unsigned)(nx|ny0|nz) < 64u);
        bool ib1 = ((unsigned)(nx|ny1|nz) < 64u);
        bool ib2 = ((unsigned)(nx|ny2|nz) < 64u);
        bool ib3 = ((unsigned)(nx|ny3|nz) < 64u);
        int npp  = ((((mx&1)<<2)|((ny0&1)<<1)|(mz&1))<<15) | ((mx>>1)<<10) | (mz>>1);
        int np0 = npp | (((ny0&63)>>1)<<5);
        int np1 = npp | (((ny1&63)>>1)<<5);
        int np2 = npp | (((ny2&63)>>1)<<5);
        int np3 = npp | (((ny3&63)>>1)<<5);
        float s0 = (ib0 && ((g_minp[np0]>>s)&1)) ? 1.f : 0.f;
        float s1 = (ib1 && ((g_minp[np1]>>s)&1)) ? 1.f : 0.f;
        float s2 = (ib2 && ((g_minp[np2]>>s)&1)) ? 1.f : 0.f;
        float s3 = (ib3 && ((g_minp[np3]>>s)&1)) ? 1.f : 0.f;
        const float4* p0 = (const float4*)(g_prob + np0*16);
        const float4* p1 = (const float4*)(g_prob + np1*16);
        const float4* p2 = (const float4*)(g_prob + np2*16);
        const float4* p3 = (const float4*)(g_prob + np3*16);
        const float4* pw = (const float4*)(sw + t*256);
        #pragma unroll
        for (int q4=0;q4<4;q4++){
            float4 u0 = p0[q4], u1 = p1[q4], u2 = p2[q4], u3 = p3[q4];
            u0.x*=s0; u0.y*=s0; u0.z*=s0; u0.w*=s0;
            u1.x*=s1; u1.y*=s1; u1.z*=s1; u1.w*=s1;
            u2.x*=s2; u2.y*=s2; u2.z*=s2; u2.w*=s2;
            u3.x*=s3; u3.y*=s3; u3.z*=s3; u3.w*=s3;
            #pragma unroll
            for (int k=0;k<4;k++){
                float a = (&u0.x)[k], b = (&u1.x)[k], c = (&u2.x)[k], d = (&u3.x)[k];
                float4 w0=pw[(q4*4+k)*4+0], w1=pw[(q4*4+k)*4+1],
                       w2=pw[(q4*4+k)*4+2], w3=pw[(q4*4+k)*4+3];
                A0[0]+=a*w0.x; A0[1]+=a*w0.y; A0[2]+=a*w0.z; A0[3]+=a*w0.w;
                A0[4]+=a*w1.x; A0[5]+=a*w1.y; A0[6]+=a*w1.z; A0[7]+=a*w1.w;
                A0[8]+=a*w2.x; A0[9]+=a*w2.y; A0[10]+=a*w2.z; A0[11]+=a*w2.w;
                A0[12]+=a*w3.x; A0[13]+=a*w3.y; A0[14]+=a*w3.z; A0[15]+=a*w3.w;
                A1[0]+=b*w0.x; A1[1]+=b*w0.y; A1[2]+=b*w0.z; A1[3]+=b*w0.w;
                A1[4]+=b*w1.x; A1[5]+=b*w1.y; A1[6]+=b*w1.z; A1[7]+=b*w1.w;
                A1[8]+=b*w2.x; A1[9]+=b*w2.y; A1[10]+=b*w2.z; A1[11]+=b*w2.w;
                A1[12]+=b*w3.x; A1[13]+=b*w3.y; A1[14]+=b*w3.z; A1[15]+=b*w3.w;
                A2[0]+=c*w0.x; A2[1]+=c*w0.y; A2[2]+=c*w0.z; A2[3]+=c*w0.w;
                A2[4]+=c*w1.x; A2[5]+=c*w1.y; A2[6]+=c*w1.z; A2[7]+=c*w1.w;
                A2[8]+=c*w2.x; A2[9]+=c*w2.y; A2[10]+=c*w2.z; A2[11]+=c*w2.w;
                A2[12]+=c*w3.x; A2[13]+=c*w3.y; A2[14]+=c*w3.z; A2[15]+=c*w3.w;
                A3[0]+=d*w0.x; A3[1]+=d*w0.y; A3[2]+=d*w0.z; A3[3]+=d*w0.w;
                A3[4]+=d*w1.x; A3[5]+=d*w1.y; A3[6]+=d*w1.z; A3[7]+=d*w1.w;
                A3[8]+=d*w2.x; A3[9]+=d*w2.y; A3[10]+=d*w2.z; A3[11]+=d*w2.w;
                A3[12]+=d*w3.x; A3[13]+=d*w3.y; A3[14]+=d*w3.z; A3[15]+=d*w3.w;
            }
        }
    }
    float* hb = g_hs[s];
    {
        float4* ph = (float4*)(hb + ((par<<15)|pi0)*16);
        ph[0]=make_float4(fmaxf(A0[0],0.f),fmaxf(A0[1],0.f),fmaxf(A0[2],0.f),fmaxf(A0[3],0.f));
        ph[1]=make_float4(fmaxf(A0[4],0.f),fmaxf(A0[5],0.f),fmaxf(A0[6],0.f),fmaxf(A0[7],0.f));
        ph[2]=make_float4(fmaxf(A0[8],0.f),fmaxf(A0[9],0.f),fmaxf(A0[10],0.f),fmaxf(A0[11],0.f));
        ph[3]=make_float4(fmaxf(A0[12],0.f),fmaxf(A0[13],0.f),fmaxf(A0[14],0.f),fmaxf(A0[15],0.f));
    }
    {
        float4* ph = (float4*)(hb + ((par<<15)|(pi0+256))*16);
        ph[0]=make_float4(fmaxf(A1[0],0.f),fmaxf(A1[1],0.f),fmaxf(A1[2],0.f),fmaxf(A1[3],0.f));
        ph[1]=make_float4(fmaxf(A1[4],0.f),fmaxf(A1[5],0.f),fmaxf(A1[6],0.f),fmaxf(A1[7],0.f));
        ph[2]=make_float4(fmaxf(A1[8],0.f),fmaxf(A1[9],0.f),fmaxf(A1[10],0.f),fmaxf(A1[11],0.f));
        ph[3]=make_float4(fmaxf(A1[12],0.f),fmaxf(A1[13],0.f),fmaxf(A1[14],0.f),fmaxf(A1[15],0.f));
    }
    {
        float4* ph = (float4*)(hb + ((par<<15)|(pi0+512))*16);
        ph[0]=make_float4(fmaxf(A2[0],0.f),fmaxf(A2[1],0.f),fmaxf(A2[2],0.f),fmaxf(A2[3],0.f));
        ph[1]=make_float4(fmaxf(A2[4],0.f),fmaxf(A2[5],0.f),fmaxf(A2[6],0.f),fmaxf(A2[7],0.f));
        ph[2]=make_float4(fmaxf(A2[8],0.f),fmaxf(A2[9],0.f),fmaxf(A2[10],0.f),fmaxf(A2[11],0.f));
        ph[3]=make_float4(fmaxf(A2[12],0.f),fmaxf(A2[13],0.f),fmaxf(A2[14],0.f),fmaxf(A2[15],0.f));
    }
    {
        float4* ph = (float4*)(hb + ((par<<15)|(pi0+768))*16);
        ph[0]=make_float4(fmaxf(A3[0],0.f),fmaxf(A3[1],0.f),fmaxf(A3[2],0.f),fmaxf(A3[3],0.f));
        ph[1]=make_float4(fmaxf(A3[4],0.f),fmaxf(A3[5],0.f),fmaxf(A3[6],0.f),fmaxf(A3[7],0.f));
        ph[2]=make_float4(fmaxf(A3[8],0.f),fmaxf(A3[9],0.f),fmaxf(A3[10],0.f),fmaxf(A3[11],0.f));
        ph[3]=make_float4(fmaxf(A3[12],0.f),fmaxf(A3[13],0.f),fmaxf(A3[14],0.f),fmaxf(A3[15],0.f));
    }
}

// ---------------- conv2: dense par-major ----------------
__global__ void __launch_bounds__(256) k_conv2_all(K2 P, float* __restrict__ out) {
    int e = blockIdx.x >> 7, ch = blockIdx.x & 127;
    int s = P.es[e];
    int par = P.par[e];
    __shared__ float sw[432];
    int tid = threadIdx.x;
    bool is5 = (s==1 || s==2);
    const float* w = P.w[s];
    if (is5) {
        for (int i=tid;i<432;i+=256) {
            int t=i>>4, c=i&15;
            int a=t/9, bb=(t/3)%3, cc=t%3;
            sw[i] = w[(((2*a)*5+2*bb)*5+2*cc)*16 + c];
        }
    } else {
        for (int i=tid;i<432;i+=256) sw[i]=w[i];
    }
    __syncthreads();
    int pi = ch*256 + tid;
    int pm = (par<<15)|pi;
    if (!((g_moutp[pm]>>s)&1)) return;
    int ox = (par>>2)&1, oy = (par>>1)&1, oz = par&1;
    int x = ((pi>>10)<<1)|ox, y = (((pi>>5)&31)<<1)|oy, z = ((pi&31)<<1)|oz;
    int sc = is5 ? 2 : 1;
    unsigned m = P.cand[e];
    const float* hbase = g_hs[s];
    float acc = P.b[s][0];
    while (m) {
        int t = __ffs(m)-1; m &= m-1;
        int nx = x + sc*(t/9-1), ny = y + sc*((t/3)%3-1), nz = z + sc*(t%3-1);
        bool inb = ((unsigned)(nx|ny|nz) < 64u);
        int mx=nx&63, my=ny&63, mz=nz&63;
        int npm = ((((mx&1)<<2)|((my&1)<<1)|(mz&1))<<15) | ((mx>>1)<<10)|((my>>1)<<5)|(mz>>1);
        float sel = (inb && ((g_minp[npm]>>s)&1)) ? 1.f : 0.f;
        const float4* pc = (const float4*)(hbase + npm*16);
        float4 c0=pc[0], c1=pc[1], c2=pc[2], c3=pc[3];
        const float* wr = sw + t*16;
        float d = c0.x*wr[0] + c0.y*wr[1] + c0.z*wr[2] + c0.w*wr[3]
                + c1.x*wr[4] + c1.y*wr[5] + c1.z*wr[6] + c1.w*wr[7]
                + c2.x*wr[8] + c2.y*wr[9] + c2.z*wr[10]+ c2.w*wr[11]
                + c3.x*wr[12]+ c3.y*wr[13]+ c3.z*wr[14]+ c3.w*wr[15];
        acc += sel*d;
    }
    out[(s<<18) | (x<<12)|(y<<6)|z] = 1.f/(1.f + expf(-acc));
}

// ---------------- host-side construction ----------------
static const int GIDH[8] = {0,5,4,3,4,2,1,5};

static unsigned mask3(int s, int par) {
    unsigned m=0;
    for (int t=0;t<27;t++) {
        int dx=t/9-1, dy=(t/3)%3-1, dz=t%3-1;
        int pn = par ^ ((((dx&1))<<2)|(((dy&1))<<1)|(dz&1));
        if (GIDH[pn] <= s-2) m |= 1u<<t;
    }
    return m;
}

// ---------------- launch ----------------
extern "C" void kernel_launch(void* const* d_in, const int* in_sizes, int n_in,
                              void* d_out, int out_size) {
    const float* x      = (const float*)d_in[0];
    const float* w_fel1 = (const float*)d_in[3];
    const float* b_fel1 = (const float*)d_in[4];
    const float* w_fel2 = (const float*)d_in[5];
    const float* b_fel2 = (const float*)d_in[6];
    const float* w_up   = (const float*)d_in[7];
    const float* b_up   = (const float*)d_in[8];
    const float* wc1    = (const float*)d_in[9];
    const float* bc1    = (const float*)d_in[10];
    const float* wc2    = (const float*)d_in[11];
    const float* bc2    = (const float*)d_in[12];
    const float* wl1    = (const float*)d_in[13];
    const float* bl1    = (const float*)d_in[14];
    const float* wl2    = (const float*)d_in[15];
    const float* bl2    = (const float*)d_in[16];
    float* out = (float*)d_out;

    K1 p1; K2 p2;
    for (int s=0;s<8;s++) {
        if (s==1 || s==2) {
            p1.w[s] = wl1 + (s-1)*125*256; p1.b[s] = bl1 + (s-1)*16;
            p2.w[s] = wl2 + (s-1)*125*16;  p2.b[s] = bl2 + (s-1);
        } else {
            int k = (s==0) ? 0 : (s-2);
            p1.w[s] = wc1 + k*27*256; p1.b[s] = bc1 + k*16;
            p2.w[s] = wc2 + k*27*16;  p2.b[s] = bc2 + k;
        }
    }
    p1.w20 = wc2; p1.b20 = bc2;

    int n1 = 0;
    for (int s=0;s<8;s++)
        for (int par=0;par<8;par++) {
            bool incl = (s<=2) ? (par==0) : (GIDH[par] <= s-2);
            if (!incl) continue;
            p1.es[n1]  = (unsigned char)s;
            p1.par[n1] = (unsigned char)par;
            p1.cand[n1] = (s==0) ? (1u<<13)
                        : (s<=2) ? 0x07FFFFFFu
                                 : mask3(s,par);
            n1++;
        }
    p1.n_ent = n1;

    int n2 = 0;
    for (int s=1;s<8;s++)
        for (int par=0;par<8;par++) {
            bool incl = (s<=2) ? (par==0) : (GIDH[par] == s-2);
            if (!incl) continue;
            p2.es[n2]  = (unsigned char)s;
            p2.par[n2] = (unsigned char)par;
            p2.cand[n2] = (s<=2) ? 0x07FFFFFFu : mask3(s,par);
            n2++;
        }
    p2.n_ent = n2;

    k_init<<<128,256>>>(x);
    k_maskfel1<<<1152,256>>>(out, w_fel1, b_fel1);
    k_fel2up<<<128,256>>>(w_fel2, b_fel2, w_up, b_up);
    k_conv1_all<<<n1*32,256>>>(p1, out);
    k_conv2_all<<<n2*128,256>>>(p2, out);
}